// round 6
// baseline (speedup 1.0000x reference)
#include <cuda_runtime.h>

// Problem constants
#define NL    6
#define DIMV  40
#define ADIMV 20
#define HHV   128
#define DINV  276
#define BATCH 131072
#define CLIPV 2.0f

// Tiling
#define TB 128
#define NT 256
#define HP 132        // h buffer pitch (floats)
#define ZP 44         // z tile pitch (floats)
#define ZAP 20        // compact z_a pitch

#define KP1 (DINV/2)  // 138 k-pairs in W1
#define KPH (HHV/2)   // 64 k-pairs in W2/W3/heads
#define KPA (ADIMV/2) // 10 k-pairs for z_a segment

// SMEM layout (floats): hA, hB, zt, za, wstp, wttp, ldet, 4 int arrays
#define SMEM_FLOATS (2*TB*HP + TB*ZP + TB*ZAP + 2*KPH*ADIMV*2 + TB)
#define SMEM_BYTES  (SMEM_FLOATS*4 + 4*NL*ADIMV*4)

// -------- pre-interleaved weights (pair over k): wp[kp][j] = (W[2kp][j], W[2kp+1][j])
__device__ __align__(16) float2 g_W1P[NL * KP1 * HHV];
__device__ __align__(16) float2 g_W2P[NL * KPH * HHV];
__device__ __align__(16) float2 g_W3P[NL * KPH * HHV];
__device__ __align__(16) float2 g_WsP[NL * KPH * ADIMV];
__device__ __align__(16) float2 g_WtP[NL * KPH * ADIMV];

__global__ void interleave_weights(const float* __restrict__ W1,
                                   const float* __restrict__ W2,
                                   const float* __restrict__ W3,
                                   const float* __restrict__ Ws,
                                   const float* __restrict__ Wt)
{
    int stride = gridDim.x * blockDim.x;
    int tid = blockIdx.x * blockDim.x + threadIdx.x;

    for (int t = tid; t < NL * KP1 * HHV; t += stride) {
        int j  = t % HHV;
        int kp = (t / HHV) % KP1;
        int l  = t / (HHV * KP1);
        const float* b = W1 + ((long long)l * DINV + 2 * kp) * HHV + j;
        g_W1P[t] = make_float2(b[0], b[HHV]);
    }
    for (int t = tid; t < NL * KPH * HHV; t += stride) {
        int j  = t % HHV;
        int kp = (t / HHV) % KPH;
        int l  = t / (HHV * KPH);
        const float* b2 = W2 + ((long long)l * HHV + 2 * kp) * HHV + j;
        const float* b3 = W3 + ((long long)l * HHV + 2 * kp) * HHV + j;
        g_W2P[t] = make_float2(b2[0], b2[HHV]);
        g_W3P[t] = make_float2(b3[0], b3[HHV]);
    }
    for (int t = tid; t < NL * KPH * ADIMV; t += stride) {
        int j  = t % ADIMV;
        int kp = (t / ADIMV) % KPH;
        int l  = t / (ADIMV * KPH);
        const float* bs_ = Ws + ((long long)l * HHV + 2 * kp) * ADIMV + j;
        const float* bt_ = Wt + ((long long)l * HHV + 2 * kp) * ADIMV + j;
        g_WsP[t] = make_float2(bs_[0], bs_[ADIMV]);
        g_WtP[t] = make_float2(bt_[0], bt_[ADIMV]);
    }
}

// -------- packed fp32x2 helpers
typedef unsigned long long u64;

__device__ __forceinline__ u64 ffma2(u64 a, u64 b, u64 c) {
    u64 d;
    asm("fma.rn.f32x2 %0, %1, %2, %3;" : "=l"(d) : "l"(a), "l"(b), "l"(c));
    return d;
}
__device__ __forceinline__ float pair_sum(u64 v) {
    float lo, hi;
    asm("mov.b64 {%0, %1}, %2;" : "=f"(lo), "=f"(hi) : "l"(v));
    return lo + hi;
}
__device__ __forceinline__ float silu_f(float v) {
    return v / (1.0f + __expf(-v));
}

// acc[i][j] lanes = (even-k partial, odd-k partial).
// A: activation rows (float, pitch pitchf), k contiguous. Wp: pair-interleaved weights.
// Pair kp covers floats [2kp, 2kp+1]; one iteration consumes pairs {kp0, kp0+1}
// = floats [2*kp0 .. 2*kp0+3]  (NOTE: offset 2*kp0 — this was the R4 bug).
__device__ __forceinline__ void gemm_pairs(const float* __restrict__ A, int pitchf,
                                           const float2* __restrict__ Wp, int kpairs,
                                           u64 (&acc)[8][8], int r0, int c0)
{
    for (int kp0 = 0; kp0 < kpairs; kp0 += 2) {
        ulonglong2 a2[8];
#pragma unroll
        for (int i = 0; i < 8; ++i)
            a2[i] = *(const ulonglong2*)&A[(r0 + i) * pitchf + 2 * kp0];
#pragma unroll
        for (int t = 0; t < 2; ++t) {
            const float2* wr = Wp + (kp0 + t) * HHV + c0;
            ulonglong2 w0 = *(const ulonglong2*)(wr);
            ulonglong2 w1 = *(const ulonglong2*)(wr + 2);
            ulonglong2 w2 = *(const ulonglong2*)(wr + 4);
            ulonglong2 w3 = *(const ulonglong2*)(wr + 6);
            u64 w[8] = {w0.x, w0.y, w1.x, w1.y, w2.x, w2.y, w3.x, w3.y};
#pragma unroll
            for (int i = 0; i < 8; ++i) {
                u64 av = t ? a2[i].y : a2[i].x;
#pragma unroll
                for (int j = 0; j < 8; ++j)
                    acc[i][j] = ffma2(av, w[j], acc[i][j]);
            }
        }
    }
}

__device__ __forceinline__ void epilogue_silu(const u64 (&acc)[8][8],
                                              const float* __restrict__ bias,
                                              float* __restrict__ dst,
                                              int r0, int c0)
{
    float bb[8];
    {
        float4 b0 = *(const float4*)(bias + c0);
        float4 b1 = *(const float4*)(bias + c0 + 4);
        bb[0] = b0.x; bb[1] = b0.y; bb[2] = b0.z; bb[3] = b0.w;
        bb[4] = b1.x; bb[5] = b1.y; bb[6] = b1.z; bb[7] = b1.w;
    }
#pragma unroll
    for (int i = 0; i < 8; ++i) {
        float4 o0, o1;
        o0.x = silu_f(pair_sum(acc[i][0]) + bb[0]);
        o0.y = silu_f(pair_sum(acc[i][1]) + bb[1]);
        o0.z = silu_f(pair_sum(acc[i][2]) + bb[2]);
        o0.w = silu_f(pair_sum(acc[i][3]) + bb[3]);
        o1.x = silu_f(pair_sum(acc[i][4]) + bb[4]);
        o1.y = silu_f(pair_sum(acc[i][5]) + bb[5]);
        o1.z = silu_f(pair_sum(acc[i][6]) + bb[6]);
        o1.w = silu_f(pair_sum(acc[i][7]) + bb[7]);
        *(float4*)&dst[(r0 + i) * HP + c0]     = o0;
        *(float4*)&dst[(r0 + i) * HP + c0 + 4] = o1;
    }
}

__global__ __launch_bounds__(NT, 1)
void biflow_kernel(const float* __restrict__ x,
                   const float* __restrict__ ctx,
                   const float* __restrict__ te,
                   const float* __restrict__ b1,
                   const float* __restrict__ b2,
                   const float* __restrict__ b3,
                   const float* __restrict__ bs,
                   const float* __restrict__ bt,
                   const int*   __restrict__ perm,
                   const int*   __restrict__ idx_a,
                   const int*   __restrict__ idx_b,
                   float* __restrict__ out)
{
    extern __shared__ float sm[];
    float*  hA   = sm;                       // TB*HP
    float*  hB   = hA + TB * HP;             // TB*HP
    float*  zt   = hB + TB * HP;             // TB*ZP
    float*  za_s = zt + TB * ZP;             // TB*ZAP (compact z_a, k-contiguous)
    float2* wstp = (float2*)(za_s + TB * ZAP);   // KPH*ADIMV pairs
    float2* wttp = wstp + KPH * ADIMV;           // KPH*ADIMV pairs
    float*  ldet = (float*)(wttp + KPH * ADIMV); // TB
    int* sa_s = (int*)(ldet + TB);           // NL*ADIM
    int* sb_s = sa_s + NL * ADIMV;
    int* da_s = sb_s + NL * ADIMV;
    int* db_s = da_s + NL * ADIMV;

    const int tid  = threadIdx.x;
    const int row0 = blockIdx.x * TB;

    // ---- init ----
    for (int idx = tid; idx < TB * DIMV; idx += NT) {
        int r = idx / DIMV, c = idx % DIMV;
        zt[r * ZP + c] = x[(row0 + r) * DIMV + c];
    }
    if (tid < TB) ldet[tid] = 0.0f;
    if (tid < NL * ADIMV) {
        int l  = tid / ADIMV;
        int ia = idx_a[tid];
        int ib = idx_b[tid];
        da_s[tid] = ia;
        db_s[tid] = ib;
        sa_s[tid] = perm[l * DIMV + ia];
        sb_s[tid] = perm[l * DIMV + ib];
    }
    __syncthreads();

    const int ty = tid >> 4, tx = tid & 15;
    const int r0 = ty * 8, c0 = tx * 8;
    const int rr = tid >> 1, q = tid & 1, j0 = q * 10;

    const float* ctxb = ctx + (long long)row0 * HHV;
    const float* teb  = te  + (long long)row0 * HHV;

    for (int l = 0; l < NL; ++l) {
        // ---- stage: compact z_a gather + head weight tiles ----
        for (int idx = tid; idx < TB * ADIMV; idx += NT) {
            int r = idx / ADIMV, k = idx % ADIMV;
            za_s[r * ZAP + k] = zt[r * ZP + sa_s[l * ADIMV + k]];
        }
        {
            const float4* wsl = (const float4*)(g_WsP + l * KPH * ADIMV);
            const float4* wtl = (const float4*)(g_WtP + l * KPH * ADIMV);
            for (int idx = tid; idx < KPH * ADIMV / 2; idx += NT) {
                ((float4*)wstp)[idx] = wsl[idx];
                ((float4*)wttp)[idx] = wtl[idx];
            }
        }
        __syncthreads();

        // ======== GEMM1: h1 = silu([z_a, ctx, te] @ W1 + b1) ========
        u64 acc[8][8];
#pragma unroll
        for (int i = 0; i < 8; ++i)
#pragma unroll
            for (int j = 0; j < 8; ++j) acc[i][j] = 0ull;

        const float2* w1p = g_W1P + l * KP1 * HHV;
        gemm_pairs(za_s, ZAP, w1p,               KPA, acc, r0, c0);
        gemm_pairs(ctxb, HHV, w1p + KPA * HHV,   KPH, acc, r0, c0);
        gemm_pairs(teb,  HHV, w1p + (KPA + KPH) * HHV, KPH, acc, r0, c0);
        epilogue_silu(acc, b1 + l * HHV, hA, r0, c0);
        __syncthreads();

        // ======== GEMM2 ========
#pragma unroll
        for (int i = 0; i < 8; ++i)
#pragma unroll
            for (int j = 0; j < 8; ++j) acc[i][j] = 0ull;
        gemm_pairs(hA, HP, g_W2P + l * KPH * HHV, KPH, acc, r0, c0);
        epilogue_silu(acc, b2 + l * HHV, hB, r0, c0);
        __syncthreads();

        // ======== GEMM3 ========
#pragma unroll
        for (int i = 0; i < 8; ++i)
#pragma unroll
            for (int j = 0; j < 8; ++j) acc[i][j] = 0ull;
        gemm_pairs(hB, HP, g_W3P + l * KPH * HHV, KPH, acc, r0, c0);
        epilogue_silu(acc, b3 + l * HHV, hA, r0, c0);
        __syncthreads();

        // ======== s/t heads + coupling ========
        u64 aS[10], aT[10];
#pragma unroll
        for (int p = 0; p < 10; ++p) { aS[p] = 0ull; aT[p] = 0ull; }

        for (int kp = 0; kp < KPH; ++kp) {
            u64 hv = *(const u64*)&hA[rr * HP + 2 * kp];
            const float2* ws = wstp + kp * ADIMV + j0;
            const float2* wt = wttp + kp * ADIMV + j0;
#pragma unroll
            for (int p = 0; p < 5; ++p) {
                ulonglong2 uw = *(const ulonglong2*)(ws + 2 * p);
                ulonglong2 vw = *(const ulonglong2*)(wt + 2 * p);
                aS[2 * p]     = ffma2(hv, uw.x, aS[2 * p]);
                aS[2 * p + 1] = ffma2(hv, uw.y, aS[2 * p + 1]);
                aT[2 * p]     = ffma2(hv, vw.x, aT[2 * p]);
                aT[2 * p + 1] = ffma2(hv, vw.y, aT[2 * p + 1]);
            }
        }

        float lsum = 0.0f;
        float za[10], yb[10];
#pragma unroll
        for (int p = 0; p < 10; ++p) {
            int j = j0 + p;
            float s = pair_sum(aS[p]) + bs[l * ADIMV + j];
            s = fminf(fmaxf(s, -CLIPV), CLIPV);
            float t  = pair_sum(aT[p]) + bt[l * ADIMV + j];
            float zb = zt[rr * ZP + sb_s[l * ADIMV + j]];
            yb[p] = fmaf(zb, __expf(s), t);
            za[p] = za_s[rr * ZAP + j];
            lsum += s;
        }
        __syncthreads();   // all gathers from zt done before scatter
#pragma unroll
        for (int p = 0; p < 10; ++p) {
            int j = j0 + p;
            zt[rr * ZP + da_s[l * ADIMV + j]] = za[p];
            zt[rr * ZP + db_s[l * ADIMV + j]] = yb[p];
        }
        float other = __shfl_down_sync(0xffffffffu, lsum, 1);
        if (q == 0) ldet[rr] += lsum + other;
        __syncthreads();
    }

    // ---- output: z (B x 40) then logdet (B) ----
    for (int idx = tid; idx < TB * DIMV; idx += NT) {
        int r = idx / DIMV, c = idx % DIMV;
        out[(long long)(row0 + r) * DIMV + c] = zt[r * ZP + c];
    }
    if (tid < TB)
        out[(long long)BATCH * DIMV + row0 + tid] = ldet[tid];
}

extern "C" void kernel_launch(void* const* d_in, const int* in_sizes, int n_in,
                              void* d_out, int out_size) {
    const float* x    = (const float*)d_in[0];
    const float* ctx  = (const float*)d_in[1];
    const float* te   = (const float*)d_in[2];
    const float* W1   = (const float*)d_in[3];
    const float* b1   = (const float*)d_in[4];
    const float* W2   = (const float*)d_in[5];
    const float* b2   = (const float*)d_in[6];
    const float* W3   = (const float*)d_in[7];
    const float* b3   = (const float*)d_in[8];
    const float* Ws   = (const float*)d_in[9];
    const float* bs   = (const float*)d_in[10];
    const float* Wt   = (const float*)d_in[11];
    const float* bt   = (const float*)d_in[12];
    const int*   perm = (const int*)d_in[13];
    const int*   ia   = (const int*)d_in[14];
    const int*   ib   = (const int*)d_in[15];
    float* out = (float*)d_out;

    interleave_weights<<<256, 256>>>(W1, W2, W3, Ws, Wt);

    cudaFuncSetAttribute(biflow_kernel,
                         cudaFuncAttributeMaxDynamicSharedMemorySize, SMEM_BYTES);

    biflow_kernel<<<BATCH / TB, NT, SMEM_BYTES>>>(
        x, ctx, te, b1, b2, b3, bs, bt, perm, ia, ib, out);
}

// round 7
// speedup vs baseline: 1.1537x; 1.1537x over previous
#include <cuda_runtime.h>

// Problem constants
#define NL    6
#define DIMV  40
#define ADIMV 20
#define HHV   128
#define DINV  276
#define BATCH 131072
#define CLIPV 2.0f

// Tiling
#define TB 128
#define NT 256
#define HP 132        // h buffer pitch (floats)
#define ZP 44         // z tile pitch (floats)
#define ZAP 20        // compact z_a pitch

#define KP1 138       // pair-rows in W1 (DIN/2)
#define KPH 64        // pair-rows in W2/W3/heads (H/2)
#define CHUNK 16      // pair-rows per staged chunk
#define ROW4 64       // float4 per pair-row (64 chunks * 16B = 1024B)

// SMEM layout (float offsets)
#define OFF_HA  0
#define OFF_HB  (TB*HP)
#define OFF_ZT  (2*TB*HP)
#define OFF_ZA  (OFF_ZT + TB*ZP)
#define OFF_WB  (OFF_ZA + TB*ZAP)              // 2 x 16KB weight chunk buffers
#define OFF_LD  (OFF_WB + 2*CHUNK*ROW4*4)
#define OFF_INT (OFF_LD + TB)
#define SMEM_BYTES (OFF_INT*4 + 4*NL*ADIMV*4)

// ---------------- pre-arranged weights in device globals ----------------
// GEMM weights: per layer, pair-rows in order; each pair-row is 64 16-byte
// chunks stored CHUNK-TRANSPOSED: chunk c (cols 2c,2c+1; each chunk =
// {(W[2k][2c],W[2k+1][2c]), (W[2k][2c+1],W[2k+1][2c+1])}) lives at position
// p = (c&3)*16 + (c>>2). Kernel copies rows linearly into smem.
__device__ __align__(16) float4 g_W1S[NL * KP1 * ROW4];  // [za 10 | ctx 64 | te 64] pair-rows
__device__ __align__(16) float4 g_W2S[NL * KPH * ROW4];
__device__ __align__(16) float4 g_W3S[NL * KPH * ROW4];
// Head weights: k-pair interleaved, linear: wp[kp*ADIM + j] = (W[2kp][j], W[2kp+1][j])
__device__ __align__(16) float2 g_WsP[NL * KPH * ADIMV];
__device__ __align__(16) float2 g_WtP[NL * KPH * ADIMV];

__global__ void prep_weights(const float* __restrict__ W1,
                             const float* __restrict__ W2,
                             const float* __restrict__ W3,
                             const float* __restrict__ Ws,
                             const float* __restrict__ Wt)
{
    int stride = gridDim.x * blockDim.x;
    int tid = blockIdx.x * blockDim.x + threadIdx.x;

    // W1S / W2S / W3S
    for (int t = tid; t < NL * KP1 * ROW4; t += stride) {
        int p  = t % ROW4;            // stored position within pair-row
        int kp = (t / ROW4) % KP1;    // pair-row
        int l  = t / (ROW4 * KP1);
        int c  = (p & 15) * 4 + (p >> 4);   // chunk index -> cols 2c, 2c+1
        const float* b = W1 + ((long long)l * DINV + 2 * kp) * HHV + 2 * c;
        g_W1S[t] = make_float4(b[0], b[HHV], b[1], b[HHV + 1]);
    }
    for (int t = tid; t < NL * KPH * ROW4; t += stride) {
        int p  = t % ROW4;
        int kp = (t / ROW4) % KPH;
        int l  = t / (ROW4 * KPH);
        int c  = (p & 15) * 4 + (p >> 4);
        const float* b2 = W2 + ((long long)l * HHV + 2 * kp) * HHV + 2 * c;
        const float* b3 = W3 + ((long long)l * HHV + 2 * kp) * HHV + 2 * c;
        g_W2S[t] = make_float4(b2[0], b2[HHV], b2[1], b2[HHV + 1]);
        g_W3S[t] = make_float4(b3[0], b3[HHV], b3[1], b3[HHV + 1]);
    }
    for (int t = tid; t < NL * KPH * ADIMV; t += stride) {
        int j  = t % ADIMV;
        int kp = (t / ADIMV) % KPH;
        int l  = t / (ADIMV * KPH);
        const float* bs_ = Ws + ((long long)l * HHV + 2 * kp) * ADIMV + j;
        const float* bt_ = Wt + ((long long)l * HHV + 2 * kp) * ADIMV + j;
        g_WsP[t] = make_float2(bs_[0], bs_[ADIMV]);
        g_WtP[t] = make_float2(bt_[0], bt_[ADIMV]);
    }
}

// ---------------- packed fp32x2 helpers ----------------
typedef unsigned long long u64;

__device__ __forceinline__ u64 ffma2(u64 a, u64 b, u64 c) {
    u64 d;
    asm("fma.rn.f32x2 %0, %1, %2, %3;" : "=l"(d) : "l"(a), "l"(b), "l"(c));
    return d;
}
__device__ __forceinline__ float pair_sum(u64 v) {
    float lo, hi;
    asm("mov.b64 {%0, %1}, %2;" : "=f"(lo), "=f"(hi) : "l"(v));
    return lo + hi;
}
__device__ __forceinline__ float silu_f(float v) {
    return v / (1.0f + __expf(-v));
}

// Copy one staged weight chunk (n4 float4s) global -> smem, linear, coalesced.
__device__ __forceinline__ void fillw(float4* __restrict__ dst,
                                      const float4* __restrict__ src,
                                      int n4, int tid)
{
    for (int i = tid; i < n4; i += NT) dst[i] = src[i];
}

// Compute npairs pair-rows against staged chunk.
// A[(r0+i)*pitchf + 2*kp0] gives 16B covering pairs kp0, kp0+1.
// Thread (tx) reads its 4 weight chunks at positions q*16+tx (contiguous across warp).
__device__ __forceinline__ void gemm_chunk(const float* __restrict__ A, int pitchf,
                                           const ulonglong2* __restrict__ Wb,
                                           int npairs, u64 (&acc)[8][8],
                                           int r0, int tx)
{
    for (int kp0 = 0; kp0 < npairs; kp0 += 2) {
        ulonglong2 a2[8];
#pragma unroll
        for (int i = 0; i < 8; ++i)
            a2[i] = *(const ulonglong2*)&A[(r0 + i) * pitchf + 2 * kp0];
#pragma unroll
        for (int t = 0; t < 2; ++t) {
            const ulonglong2* wrow = Wb + (kp0 + t) * (ROW4 / 1) ;  // 64 u64x2 per row
            ulonglong2 w4[4];
#pragma unroll
            for (int q = 0; q < 4; ++q)
                w4[q] = wrow[q * 16 + tx];
#pragma unroll
            for (int i = 0; i < 8; ++i) {
                u64 av = t ? a2[i].y : a2[i].x;
#pragma unroll
                for (int q = 0; q < 4; ++q) {
                    acc[i][2 * q]     = ffma2(av, w4[q].x, acc[i][2 * q]);
                    acc[i][2 * q + 1] = ffma2(av, w4[q].y, acc[i][2 * q + 1]);
                }
            }
        }
    }
}

__device__ __forceinline__ void epilogue_silu(const u64 (&acc)[8][8],
                                              const float* __restrict__ bias,
                                              float* __restrict__ dst,
                                              int r0, int c0)
{
    float bb[8];
    {
        float4 b0 = *(const float4*)(bias + c0);
        float4 b1 = *(const float4*)(bias + c0 + 4);
        bb[0] = b0.x; bb[1] = b0.y; bb[2] = b0.z; bb[3] = b0.w;
        bb[4] = b1.x; bb[5] = b1.y; bb[6] = b1.z; bb[7] = b1.w;
    }
#pragma unroll
    for (int i = 0; i < 8; ++i) {
        float4 o0, o1;
        o0.x = silu_f(pair_sum(acc[i][0]) + bb[0]);
        o0.y = silu_f(pair_sum(acc[i][1]) + bb[1]);
        o0.z = silu_f(pair_sum(acc[i][2]) + bb[2]);
        o0.w = silu_f(pair_sum(acc[i][3]) + bb[3]);
        o1.x = silu_f(pair_sum(acc[i][4]) + bb[4]);
        o1.y = silu_f(pair_sum(acc[i][5]) + bb[5]);
        o1.z = silu_f(pair_sum(acc[i][6]) + bb[6]);
        o1.w = silu_f(pair_sum(acc[i][7]) + bb[7]);
        *(float4*)&dst[(r0 + i) * HP + c0]     = o0;
        *(float4*)&dst[(r0 + i) * HP + c0 + 4] = o1;
    }
}

#define ZERO_ACC()                              \
    _Pragma("unroll")                           \
    for (int i = 0; i < 8; ++i)                 \
        _Pragma("unroll")                       \
        for (int j = 0; j < 8; ++j) acc[i][j] = 0ull;

__global__ __launch_bounds__(NT, 1)
void biflow_kernel(const float* __restrict__ x,
                   const float* __restrict__ ctx,
                   const float* __restrict__ te,
                   const float* __restrict__ b1,
                   const float* __restrict__ b2,
                   const float* __restrict__ b3,
                   const float* __restrict__ bs,
                   const float* __restrict__ bt,
                   const int*   __restrict__ perm,
                   const int*   __restrict__ idx_a,
                   const int*   __restrict__ idx_b,
                   float* __restrict__ out)
{
    extern __shared__ float sm[];
    float*  hA   = sm + OFF_HA;
    float*  hB   = sm + OFF_HB;
    float*  zt   = sm + OFF_ZT;
    float*  za_s = sm + OFF_ZA;
    float*  wb   = sm + OFF_WB;              // two 16KB chunk buffers
    float*  ldet = sm + OFF_LD;
    int* sa_s = (int*)(sm + OFF_INT);
    int* sb_s = sa_s + NL * ADIMV;
    int* da_s = sb_s + NL * ADIMV;
    int* db_s = da_s + NL * ADIMV;

    float4* wb4[2] = { (float4*)wb, (float4*)(wb + CHUNK * ROW4 * 4) };

    const int tid  = threadIdx.x;
    const int row0 = blockIdx.x * TB;

    // ---- init ----
    for (int idx = tid; idx < TB * DIMV; idx += NT) {
        int r = idx / DIMV, c = idx % DIMV;
        zt[r * ZP + c] = x[(row0 + r) * DIMV + c];
    }
    if (tid < TB) ldet[tid] = 0.0f;
    if (tid < NL * ADIMV) {
        int l  = tid / ADIMV;
        int ia = idx_a[tid];
        int ib = idx_b[tid];
        da_s[tid] = ia;
        db_s[tid] = ib;
        sa_s[tid] = perm[l * DIMV + ia];
        sb_s[tid] = perm[l * DIMV + ib];
    }
    __syncthreads();

    const int ty = tid >> 4, tx = tid & 15;
    const int r0 = ty * 8, c0 = tx * 8;
    const int rr = tid >> 1, q = tid & 1, j0 = q * 10;

    const float* ctxb = ctx + (long long)row0 * HHV;
    const float* teb  = te  + (long long)row0 * HHV;

    for (int l = 0; l < NL; ++l) {
        // ---- stage compact z_a (gathered, k-contiguous) ----
        for (int idx = tid; idx < TB * ADIMV; idx += NT) {
            int r = idx / ADIMV, k = idx % ADIMV;
            za_s[r * ZAP + k] = zt[r * ZP + sa_s[l * ADIMV + k]];
        }

        u64 acc[8][8];

        // ======== GEMM1: 9 chunks [za(10) | ctx x4 | te x4] ========
        ZERO_ACC();
        const float4* w1src = g_W1S + l * KP1 * ROW4;
        fillw(wb4[0], w1src, 10 * ROW4, tid);
        __syncthreads();
        for (int i = 0; i < 9; ++i) {
            if (i < 8)
                fillw(wb4[(i + 1) & 1], w1src + (10 + 16 * i) * ROW4, CHUNK * ROW4, tid);
            const float* A; int pitch; int npairs;
            if (i == 0)      { A = za_s;                 pitch = ZAP; npairs = 10; }
            else if (i <= 4) { A = ctxb + (i - 1) * 32;  pitch = HHV; npairs = CHUNK; }
            else             { A = teb  + (i - 5) * 32;  pitch = HHV; npairs = CHUNK; }
            gemm_chunk(A, pitch, (const ulonglong2*)wb4[i & 1], npairs, acc, r0, tx);
            __syncthreads();
        }
        epilogue_silu(acc, b1 + l * HHV, hA, r0, c0);

        // ======== GEMM2: 4 chunks ========
        ZERO_ACC();
        const float4* w2src = g_W2S + l * KPH * ROW4;
        fillw(wb4[0], w2src, CHUNK * ROW4, tid);
        __syncthreads();
        for (int i = 0; i < 4; ++i) {
            if (i < 3)
                fillw(wb4[(i + 1) & 1], w2src + 16 * (i + 1) * ROW4, CHUNK * ROW4, tid);
            gemm_chunk(hA + 32 * i, HP, (const ulonglong2*)wb4[i & 1], CHUNK, acc, r0, tx);
            __syncthreads();
        }
        epilogue_silu(acc, b2 + l * HHV, hB, r0, c0);

        // ======== GEMM3: 4 chunks ========
        ZERO_ACC();
        const float4* w3src = g_W3S + l * KPH * ROW4;
        fillw(wb4[0], w3src, CHUNK * ROW4, tid);
        __syncthreads();
        for (int i = 0; i < 4; ++i) {
            if (i < 3)
                fillw(wb4[(i + 1) & 1], w3src + 16 * (i + 1) * ROW4, CHUNK * ROW4, tid);
            gemm_chunk(hB + 32 * i, HP, (const ulonglong2*)wb4[i & 1], CHUNK, acc, r0, tx);
            __syncthreads();
        }
        epilogue_silu(acc, b3 + l * HHV, hA, r0, c0);

        // ======== stage head weights into the (now free) W buffer ========
        float2* wstp = (float2*)wb;                      // 10240 B
        float2* wttp = (float2*)(wb + 2 * KPH * ADIMV);  // next 10240 B
        {
            const float4* wsl = (const float4*)(g_WsP + l * KPH * ADIMV);
            const float4* wtl = (const float4*)(g_WtP + l * KPH * ADIMV);
            for (int idx = tid; idx < KPH * ADIMV / 2; idx += NT) {
                ((float4*)wstp)[idx] = wsl[idx];
                ((float4*)wttp)[idx] = wtl[idx];
            }
        }
        __syncthreads();   // heads weights ready + hA (GEMM3 epilogue) visible

        // ======== s/t heads + coupling ========
        u64 aS[10], aT[10];
#pragma unroll
        for (int p = 0; p < 10; ++p) { aS[p] = 0ull; aT[p] = 0ull; }

        for (int kp = 0; kp < KPH; ++kp) {
            u64 hv = *(const u64*)&hA[rr * HP + 2 * kp];
            const float2* ws = wstp + kp * ADIMV + j0;
            const float2* wt = wttp + kp * ADIMV + j0;
#pragma unroll
            for (int p = 0; p < 5; ++p) {
                ulonglong2 uw = *(const ulonglong2*)(ws + 2 * p);
                ulonglong2 vw = *(const ulonglong2*)(wt + 2 * p);
                aS[2 * p]     = ffma2(hv, uw.x, aS[2 * p]);
                aS[2 * p + 1] = ffma2(hv, uw.y, aS[2 * p + 1]);
                aT[2 * p]     = ffma2(hv, vw.x, aT[2 * p]);
                aT[2 * p + 1] = ffma2(hv, vw.y, aT[2 * p + 1]);
            }
        }

        float lsum = 0.0f;
        float za[10], yb[10];
#pragma unroll
        for (int p = 0; p < 10; ++p) {
            int j = j0 + p;
            float s = pair_sum(aS[p]) + bs[l * ADIMV + j];
            s = fminf(fmaxf(s, -CLIPV), CLIPV);
            float t  = pair_sum(aT[p]) + bt[l * ADIMV + j];
            float zb = zt[rr * ZP + sb_s[l * ADIMV + j]];
            yb[p] = fmaf(zb, __expf(s), t);
            za[p] = za_s[rr * ZAP + j];
            lsum += s;
        }
        __syncthreads();   // all gathers from zt done before scatter
#pragma unroll
        for (int p = 0; p < 10; ++p) {
            int j = j0 + p;
            zt[rr * ZP + da_s[l * ADIMV + j]] = za[p];
            zt[rr * ZP + db_s[l * ADIMV + j]] = yb[p];
        }
        float other = __shfl_down_sync(0xffffffffu, lsum, 1);
        if (q == 0) ldet[rr] += lsum + other;
        __syncthreads();
    }

    // ---- output: z (B x 40) then logdet (B) ----
    for (int idx = tid; idx < TB * DIMV; idx += NT) {
        int r = idx / DIMV, c = idx % DIMV;
        out[(long long)(row0 + r) * DIMV + c] = zt[r * ZP + c];
    }
    if (tid < TB)
        out[(long long)BATCH * DIMV + row0 + tid] = ldet[tid];
}

extern "C" void kernel_launch(void* const* d_in, const int* in_sizes, int n_in,
                              void* d_out, int out_size) {
    const float* x    = (const float*)d_in[0];
    const float* ctx  = (const float*)d_in[1];
    const float* te   = (const float*)d_in[2];
    const float* W1   = (const float*)d_in[3];
    const float* b1   = (const float*)d_in[4];
    const float* W2   = (const float*)d_in[5];
    const float* b2   = (const float*)d_in[6];
    const float* W3   = (const float*)d_in[7];
    const float* b3   = (const float*)d_in[8];
    const float* Ws   = (const float*)d_in[9];
    const float* bs   = (const float*)d_in[10];
    const float* Wt   = (const float*)d_in[11];
    const float* bt   = (const float*)d_in[12];
    const int*   perm = (const int*)d_in[13];
    const int*   ia   = (const int*)d_in[14];
    const int*   ib   = (const int*)d_in[15];
    float* out = (float*)d_out;

    prep_weights<<<256, 256>>>(W1, W2, W3, Ws, Wt);

    cudaFuncSetAttribute(biflow_kernel,
                         cudaFuncAttributeMaxDynamicSharedMemorySize, SMEM_BYTES);

    biflow_kernel<<<BATCH / TB, NT, SMEM_BYTES>>>(
        x, ctx, te, b1, b2, b3, bs, bt, perm, ia, ib, out);
}

// round 8
// speedup vs baseline: 1.2673x; 1.0984x over previous
#include <cuda_runtime.h>

// Problem constants
#define NL    6
#define DIMV  40
#define ADIMV 20
#define HHV   128
#define DINV  276
#define BATCH 131072
#define CLIPV 2.0f

// Tiling
#define TB 128
#define NT 512
#define RT 4          // rows per thread
#define HP 132        // h buffer pitch (floats)
#define ZP 44         // z tile pitch (floats)
#define ZAP 20        // compact z_a pitch

#define KP1 138       // pair-rows in W1 (DIN/2)
#define KPH 64        // pair-rows in W2/W3/heads (H/2)
#define CHUNK 16      // pair-rows per staged chunk
#define ROW4 64       // float4 per pair-row (64 chunks * 16B = 1024B)

// SMEM layout (float offsets)
#define OFF_HA  0
#define OFF_HB  (TB*HP)
#define OFF_ZT  (2*TB*HP)
#define OFF_ZA  (OFF_ZT + TB*ZP)
#define OFF_WB  (OFF_ZA + TB*ZAP)              // 2 x 16KB weight chunk buffers
#define OFF_LD  (OFF_WB + 2*CHUNK*ROW4*4)
#define OFF_INT (OFF_LD + TB)
#define SMEM_BYTES (OFF_INT*4 + 4*NL*ADIMV*4)

// ---------------- pre-arranged weights in device globals ----------------
// Pair-row = 64 16-byte chunks, CHUNK-TRANSPOSED: chunk c (cols 2c,2c+1) at
// position p = (c&3)*16 + (c>>2). Kernel copies rows linearly into smem;
// thread tx reads positions q*16+tx (contiguous across warp, conflict-free).
__device__ __align__(16) float4 g_W1S[NL * KP1 * ROW4];
__device__ __align__(16) float4 g_W2S[NL * KPH * ROW4];
__device__ __align__(16) float4 g_W3S[NL * KPH * ROW4];
// Head weights: k-pair interleaved, linear: wp[kp*ADIM + j] = (W[2kp][j], W[2kp+1][j])
__device__ __align__(16) float2 g_WsP[NL * KPH * ADIMV];
__device__ __align__(16) float2 g_WtP[NL * KPH * ADIMV];

__global__ void prep_weights(const float* __restrict__ W1,
                             const float* __restrict__ W2,
                             const float* __restrict__ W3,
                             const float* __restrict__ Ws,
                             const float* __restrict__ Wt)
{
    int stride = gridDim.x * blockDim.x;
    int tid = blockIdx.x * blockDim.x + threadIdx.x;

    for (int t = tid; t < NL * KP1 * ROW4; t += stride) {
        int p  = t % ROW4;
        int kp = (t / ROW4) % KP1;
        int l  = t / (ROW4 * KP1);
        int c  = (p & 15) * 4 + (p >> 4);
        const float* b = W1 + ((long long)l * DINV + 2 * kp) * HHV + 2 * c;
        g_W1S[t] = make_float4(b[0], b[HHV], b[1], b[HHV + 1]);
    }
    for (int t = tid; t < NL * KPH * ROW4; t += stride) {
        int p  = t % ROW4;
        int kp = (t / ROW4) % KPH;
        int l  = t / (ROW4 * KPH);
        int c  = (p & 15) * 4 + (p >> 4);
        const float* b2 = W2 + ((long long)l * HHV + 2 * kp) * HHV + 2 * c;
        const float* b3 = W3 + ((long long)l * HHV + 2 * kp) * HHV + 2 * c;
        g_W2S[t] = make_float4(b2[0], b2[HHV], b2[1], b2[HHV + 1]);
        g_W3S[t] = make_float4(b3[0], b3[HHV], b3[1], b3[HHV + 1]);
    }
    for (int t = tid; t < NL * KPH * ADIMV; t += stride) {
        int j  = t % ADIMV;
        int kp = (t / ADIMV) % KPH;
        int l  = t / (ADIMV * KPH);
        const float* bs_ = Ws + ((long long)l * HHV + 2 * kp) * ADIMV + j;
        const float* bt_ = Wt + ((long long)l * HHV + 2 * kp) * ADIMV + j;
        g_WsP[t] = make_float2(bs_[0], bs_[ADIMV]);
        g_WtP[t] = make_float2(bt_[0], bt_[ADIMV]);
    }
}

// ---------------- packed fp32x2 helpers ----------------
typedef unsigned long long u64;

__device__ __forceinline__ u64 ffma2(u64 a, u64 b, u64 c) {
    u64 d;
    asm("fma.rn.f32x2 %0, %1, %2, %3;" : "=l"(d) : "l"(a), "l"(b), "l"(c));
    return d;
}
__device__ __forceinline__ float pair_sum(u64 v) {
    float lo, hi;
    asm("mov.b64 {%0, %1}, %2;" : "=f"(lo), "=f"(hi) : "l"(v));
    return lo + hi;
}
__device__ __forceinline__ float silu_f(float v) {
    return v / (1.0f + __expf(-v));
}

__device__ __forceinline__ void fillw(float4* __restrict__ dst,
                                      const float4* __restrict__ src,
                                      int n4, int tid)
{
    for (int i = tid; i < n4; i += NT) dst[i] = src[i];
}

// Compute npairs pair-rows of staged weights against activations.
// acc lanes = (even-k partial, odd-k partial). RT=4 rows, 8 cols per thread.
__device__ __forceinline__ void gemm_chunk(const float* __restrict__ A, int pitchf,
                                           const ulonglong2* __restrict__ Wb,
                                           int npairs, u64 (&acc)[RT][8],
                                           int r0, int tx)
{
    for (int kp0 = 0; kp0 < npairs; kp0 += 2) {
        ulonglong2 a2[RT];
#pragma unroll
        for (int i = 0; i < RT; ++i)
            a2[i] = *(const ulonglong2*)&A[(r0 + i) * pitchf + 2 * kp0];
#pragma unroll
        for (int t = 0; t < 2; ++t) {
            const ulonglong2* wrow = Wb + (kp0 + t) * 64;  // 64 u64x2 per pair-row
            ulonglong2 w4[4];
#pragma unroll
            for (int q = 0; q < 4; ++q)
                w4[q] = wrow[q * 16 + tx];
#pragma unroll
            for (int i = 0; i < RT; ++i) {
                u64 av = t ? a2[i].y : a2[i].x;
#pragma unroll
                for (int q = 0; q < 4; ++q) {
                    acc[i][2 * q]     = ffma2(av, w4[q].x, acc[i][2 * q]);
                    acc[i][2 * q + 1] = ffma2(av, w4[q].y, acc[i][2 * q + 1]);
                }
            }
        }
    }
}

__device__ __forceinline__ void epilogue_silu(const u64 (&acc)[RT][8],
                                              const float* __restrict__ bias,
                                              float* __restrict__ dst,
                                              int r0, int c0)
{
    float bb[8];
    {
        float4 b0 = *(const float4*)(bias + c0);
        float4 b1 = *(const float4*)(bias + c0 + 4);
        bb[0] = b0.x; bb[1] = b0.y; bb[2] = b0.z; bb[3] = b0.w;
        bb[4] = b1.x; bb[5] = b1.y; bb[6] = b1.z; bb[7] = b1.w;
    }
#pragma unroll
    for (int i = 0; i < RT; ++i) {
        float4 o0, o1;
        o0.x = silu_f(pair_sum(acc[i][0]) + bb[0]);
        o0.y = silu_f(pair_sum(acc[i][1]) + bb[1]);
        o0.z = silu_f(pair_sum(acc[i][2]) + bb[2]);
        o0.w = silu_f(pair_sum(acc[i][3]) + bb[3]);
        o1.x = silu_f(pair_sum(acc[i][4]) + bb[4]);
        o1.y = silu_f(pair_sum(acc[i][5]) + bb[5]);
        o1.z = silu_f(pair_sum(acc[i][6]) + bb[6]);
        o1.w = silu_f(pair_sum(acc[i][7]) + bb[7]);
        *(float4*)&dst[(r0 + i) * HP + c0]     = o0;
        *(float4*)&dst[(r0 + i) * HP + c0 + 4] = o1;
    }
}

#define ZERO_ACC()                              \
    _Pragma("unroll")                           \
    for (int i = 0; i < RT; ++i)                \
        _Pragma("unroll")                       \
        for (int j = 0; j < 8; ++j) acc[i][j] = 0ull;

__global__ __launch_bounds__(NT, 1)
void biflow_kernel(const float* __restrict__ x,
                   const float* __restrict__ ctx,
                   const float* __restrict__ te,
                   const float* __restrict__ b1,
                   const float* __restrict__ b2,
                   const float* __restrict__ b3,
                   const float* __restrict__ bs,
                   const float* __restrict__ bt,
                   const int*   __restrict__ perm,
                   const int*   __restrict__ idx_a,
                   const int*   __restrict__ idx_b,
                   float* __restrict__ out)
{
    extern __shared__ float sm[];
    float*  hA   = sm + OFF_HA;
    float*  hB   = sm + OFF_HB;
    float*  zt   = sm + OFF_ZT;
    float*  za_s = sm + OFF_ZA;
    float*  wb   = sm + OFF_WB;
    float*  ldet = sm + OFF_LD;
    int* sa_s = (int*)(sm + OFF_INT);
    int* sb_s = sa_s + NL * ADIMV;
    int* da_s = sb_s + NL * ADIMV;
    int* db_s = da_s + NL * ADIMV;

    float4* wb4[2] = { (float4*)wb, (float4*)(wb + CHUNK * ROW4 * 4) };

    const int tid  = threadIdx.x;
    const int row0 = blockIdx.x * TB;

    // ---- init ----
    for (int idx = tid; idx < TB * DIMV; idx += NT) {
        int r = idx / DIMV, c = idx % DIMV;
        zt[r * ZP + c] = x[(row0 + r) * DIMV + c];
    }
    if (tid < TB) ldet[tid] = 0.0f;
    if (tid < NL * ADIMV) {
        int l  = tid / ADIMV;
        int ia = idx_a[tid];
        int ib = idx_b[tid];
        da_s[tid] = ia;
        db_s[tid] = ib;
        sa_s[tid] = perm[l * DIMV + ia];
        sb_s[tid] = perm[l * DIMV + ib];
    }
    __syncthreads();

    const int ty = tid >> 4, tx = tid & 15;   // ty 0..31, tx 0..15
    const int r0 = ty * RT, c0 = tx * 8;
    const int rr = tid >> 2, q = tid & 3, j0 = q * 5;   // head: 4 thr/row, 5 cols

    const float* ctxb = ctx + (long long)row0 * HHV;
    const float* teb  = te  + (long long)row0 * HHV;

    for (int l = 0; l < NL; ++l) {
        // ---- stage compact z_a (gathered, k-contiguous) ----
        for (int idx = tid; idx < TB * ADIMV; idx += NT) {
            int r = idx / ADIMV, k = idx % ADIMV;
            za_s[r * ZAP + k] = zt[r * ZP + sa_s[l * ADIMV + k]];
        }

        u64 acc[RT][8];

        // ======== GEMM1: 9 chunks [za(10) | ctx x4 | te x4] ========
        ZERO_ACC();
        const float4* w1src = g_W1S + l * KP1 * ROW4;
        fillw(wb4[0], w1src, 10 * ROW4, tid);
        __syncthreads();
        for (int i = 0; i < 9; ++i) {
            if (i < 8)
                fillw(wb4[(i + 1) & 1], w1src + (10 + 16 * i) * ROW4, CHUNK * ROW4, tid);
            const float* A; int pitch; int npairs;
            if (i == 0)      { A = za_s;                 pitch = ZAP; npairs = 10; }
            else if (i <= 4) { A = ctxb + (i - 1) * 32;  pitch = HHV; npairs = CHUNK; }
            else             { A = teb  + (i - 5) * 32;  pitch = HHV; npairs = CHUNK; }
            gemm_chunk(A, pitch, (const ulonglong2*)wb4[i & 1], npairs, acc, r0, tx);
            __syncthreads();
        }
        epilogue_silu(acc, b1 + l * HHV, hA, r0, c0);

        // ======== GEMM2: 4 chunks ========
        ZERO_ACC();
        const float4* w2src = g_W2S + l * KPH * ROW4;
        fillw(wb4[0], w2src, CHUNK * ROW4, tid);
        __syncthreads();
        for (int i = 0; i < 4; ++i) {
            if (i < 3)
                fillw(wb4[(i + 1) & 1], w2src + 16 * (i + 1) * ROW4, CHUNK * ROW4, tid);
            gemm_chunk(hA + 32 * i, HP, (const ulonglong2*)wb4[i & 1], CHUNK, acc, r0, tx);
            __syncthreads();
        }
        epilogue_silu(acc, b2 + l * HHV, hB, r0, c0);

        // ======== GEMM3: 4 chunks ========
        ZERO_ACC();
        const float4* w3src = g_W3S + l * KPH * ROW4;
        fillw(wb4[0], w3src, CHUNK * ROW4, tid);
        __syncthreads();
        for (int i = 0; i < 4; ++i) {
            if (i < 3)
                fillw(wb4[(i + 1) & 1], w3src + 16 * (i + 1) * ROW4, CHUNK * ROW4, tid);
            gemm_chunk(hB + 32 * i, HP, (const ulonglong2*)wb4[i & 1], CHUNK, acc, r0, tx);
            __syncthreads();
        }
        epilogue_silu(acc, b3 + l * HHV, hA, r0, c0);

        // ======== stage head weights into the (now free) W buffer ========
        float2* wstp = (float2*)wb;
        float2* wttp = (float2*)(wb + 2 * KPH * ADIMV);
        {
            const float4* wsl = (const float4*)(g_WsP + l * KPH * ADIMV);
            const float4* wtl = (const float4*)(g_WtP + l * KPH * ADIMV);
            for (int idx = tid; idx < KPH * ADIMV / 2; idx += NT) {
                ((float4*)wstp)[idx] = wsl[idx];
                ((float4*)wttp)[idx] = wtl[idx];
            }
        }
        __syncthreads();   // head weights ready + hA visible

        // ======== s/t heads + coupling: 4 threads/row, 5 cols each ========
        u64 aS[5], aT[5];
#pragma unroll
        for (int p = 0; p < 5; ++p) { aS[p] = 0ull; aT[p] = 0ull; }

        for (int kp = 0; kp < KPH; ++kp) {
            u64 hv = *(const u64*)&hA[rr * HP + 2 * kp];
            const u64* ws8 = (const u64*)(wstp + kp * ADIMV + j0);
            const u64* wt8 = (const u64*)(wttp + kp * ADIMV + j0);
#pragma unroll
            for (int p = 0; p < 5; ++p) {
                aS[p] = ffma2(hv, ws8[p], aS[p]);
                aT[p] = ffma2(hv, wt8[p], aT[p]);
            }
        }

        float lsum = 0.0f;
        float za[5], yb[5];
#pragma unroll
        for (int p = 0; p < 5; ++p) {
            int j = j0 + p;
            float s = pair_sum(aS[p]) + bs[l * ADIMV + j];
            s = fminf(fmaxf(s, -CLIPV), CLIPV);
            float t  = pair_sum(aT[p]) + bt[l * ADIMV + j];
            float zb = zt[rr * ZP + sb_s[l * ADIMV + j]];
            yb[p] = fmaf(zb, __expf(s), t);
            za[p] = za_s[rr * ZAP + j];
            lsum += s;
        }
        __syncthreads();   // all gathers from zt done before scatter
#pragma unroll
        for (int p = 0; p < 5; ++p) {
            int j = j0 + p;
            zt[rr * ZP + da_s[l * ADIMV + j]] = za[p];
            zt[rr * ZP + db_s[l * ADIMV + j]] = yb[p];
        }
        // reduce lsum over the 4 lanes of this row (lanes are consecutive)
        lsum += __shfl_down_sync(0xffffffffu, lsum, 1);
        lsum += __shfl_down_sync(0xffffffffu, lsum, 2);
        if (q == 0) ldet[rr] += lsum;
        __syncthreads();
    }

    // ---- output: z (B x 40) then logdet (B) ----
    for (int idx = tid; idx < TB * DIMV; idx += NT) {
        int r = idx / DIMV, c = idx % DIMV;
        out[(long long)(row0 + r) * DIMV + c] = zt[r * ZP + c];
    }
    if (tid < TB)
        out[(long long)BATCH * DIMV + row0 + tid] = ldet[tid];
}

extern "C" void kernel_launch(void* const* d_in, const int* in_sizes, int n_in,
                              void* d_out, int out_size) {
    const float* x    = (const float*)d_in[0];
    const float* ctx  = (const float*)d_in[1];
    const float* te   = (const float*)d_in[2];
    const float* W1   = (const float*)d_in[3];
    const float* b1   = (const float*)d_in[4];
    const float* W2   = (const float*)d_in[5];
    const float* b2   = (const float*)d_in[6];
    const float* W3   = (const float*)d_in[7];
    const float* b3   = (const float*)d_in[8];
    const float* Ws   = (const float*)d_in[9];
    const float* bs   = (const float*)d_in[10];
    const float* Wt   = (const float*)d_in[11];
    const float* bt   = (const float*)d_in[12];
    const int*   perm = (const int*)d_in[13];
    const int*   ia   = (const int*)d_in[14];
    const int*   ib   = (const int*)d_in[15];
    float* out = (float*)d_out;

    prep_weights<<<256, 256>>>(W1, W2, W3, Ws, Wt);

    cudaFuncSetAttribute(biflow_kernel,
                         cudaFuncAttributeMaxDynamicSharedMemorySize, SMEM_BYTES);

    biflow_kernel<<<BATCH / TB, NT, SMEM_BYTES>>>(
        x, ctx, te, b1, b2, b3, bs, bt, perm, ia, ib, out);
}

// round 11
// speedup vs baseline: 1.4280x; 1.1268x over previous
#include <cuda_runtime.h>
#include <cuda_bf16.h>
#include <mma.h>
#include <cstdint>

using namespace nvcuda;

// Problem constants
#define NL    6
#define DIMV  40
#define ADIMV 20
#define HHV   128
#define DINV  276
#define BATCH 131072
#define CLIPV 2.0f

#define TB 128
#define NT 512
#define ZP 44

// pitches
#define PA 136      // activation tile pitch (bf16 elems)
#define PW 136      // weight tile pitch (bf16 elems)
#define PC 132      // C staging pitch (f32 elems)
#define PCH 68      // heads C staging pitch (f32)
#define PH 72       // heads weight pitch (bf16)

#define ALO (128*PA)        // act lo-tile element offset

// per-layer weight image element counts (hi tile + lo tile)
#define E_ZA  (2*32*PA)     // 8704
#define E_C   (2*128*PW)    // 34816
#define E_HD  (2*128*PH)    // 18432

// SMEM byte offsets
#define SM_ACT  0
#define SM_WB   (2*128*PA*2)                 // 69632
#define SM_ZT   (SM_WB + 2*128*PW*2)         // 139264
#define SM_LDET (SM_ZT + TB*ZP*4)            // 161792
#define SM_IDX  (SM_LDET + TB*4)             // 162304
#define SMEM_TOTAL (SM_IDX + 4*NL*ADIMV*4)   // 164224

typedef __nv_bfloat16 bf16;

// pre-split, pre-laid-out weight images (hi tile then lo tile, exact SMEM image)
__device__ __align__(16) bf16 g_Wza[NL * E_ZA];
__device__ __align__(16) bf16 g_Wc [NL * E_C];
__device__ __align__(16) bf16 g_Wt_[NL * E_C];
__device__ __align__(16) bf16 g_W2 [NL * E_C];
__device__ __align__(16) bf16 g_W3 [NL * E_C];
__device__ __align__(16) bf16 g_Whd[NL * E_HD];

__device__ __forceinline__ void split_store(bf16* hi_p, bf16* lo_p, float v) {
    bf16 h = __float2bfloat16(v);
    bf16 lo = __float2bfloat16(v - __bfloat162float(h));
    *hi_p = h; *lo_p = lo;
}

__global__ void prep_weights(const float* __restrict__ W1,
                             const float* __restrict__ W2,
                             const float* __restrict__ W3,
                             const float* __restrict__ Ws,
                             const float* __restrict__ Wt)
{
    int stride = gridDim.x * blockDim.x;
    int tid0 = blockIdx.x * blockDim.x + threadIdx.x;

    // za: K=32 (rows 20..31 zero), N cols 0..135 (>=128 zero)
    for (int t = tid0; t < NL * 32 * PA; t += stride) {
        int c = t % PA, k = (t / PA) % 32, l = t / (PA * 32);
        float v = (k < ADIMV && c < HHV) ? W1[((long long)l * DINV + k) * HHV + c] : 0.0f;
        bf16* base = g_Wza + (size_t)l * E_ZA;
        split_store(base + k * PA + c, base + 32 * PA + k * PA + c, v);
    }
    // ctx / te / W2 / W3: K=128
    for (int t = tid0; t < NL * 128 * PW; t += stride) {
        int c = t % PW, k = (t / PW) % 128, l = t / (PW * 128);
        float vc = 0.f, vt = 0.f, v2 = 0.f, v3 = 0.f;
        if (c < HHV) {
            vc = W1[((long long)l * DINV + ADIMV + k) * HHV + c];
            vt = W1[((long long)l * DINV + ADIMV + HHV + k) * HHV + c];
            v2 = W2[((long long)l * HHV + k) * HHV + c];
            v3 = W3[((long long)l * HHV + k) * HHV + c];
        }
        size_t o = (size_t)l * E_C + (size_t)k * PW + c;
        size_t olo = o + (size_t)128 * PW;
        split_store(g_Wc + o,  g_Wc + olo,  vc);
        split_store(g_Wt_ + o, g_Wt_ + olo, vt);
        split_store(g_W2 + o,  g_W2 + olo,  v2);
        split_store(g_W3 + o,  g_W3 + olo,  v3);
    }
    // heads: K=128, N=64 packed [Ws(20)|Wt(20)|zeros]
    for (int t = tid0; t < NL * 128 * PH; t += stride) {
        int c = t % PH, k = (t / PH) % 128, l = t / (PH * 128);
        float v = 0.0f;
        if (c < ADIMV)           v = Ws[((long long)l * HHV + k) * ADIMV + c];
        else if (c < 2 * ADIMV)  v = Wt[((long long)l * HHV + k) * ADIMV + (c - ADIMV)];
        bf16* base = g_Whd + (size_t)l * E_HD;
        split_store(base + k * PH + c, base + 128 * PH + k * PH + c, v);
    }
}

__device__ __forceinline__ float silu_f(float v) { return v / (1.0f + __expf(-v)); }

__device__ __forceinline__ void cpimg(char* dst, const bf16* src, int bytes, int tid) {
    float4* d = (float4*)dst;
    const float4* s = (const float4*)src;
    int n = bytes >> 4;
    for (int i = tid; i < n; i += NT) d[i] = s[i];
}

typedef wmma::fragment<wmma::matrix_a, 16, 16, 16, bf16, wmma::row_major> FragA;
typedef wmma::fragment<wmma::matrix_b, 16, 16, 16, bf16, wmma::row_major> FragB;
typedef wmma::fragment<wmma::accumulator, 16, 16, 16, float> FragC;

// 3-term split MMA over one staged K-chunk. acc[2][2] covers 32x32.
__device__ __forceinline__ void gemm_chunk(const bf16* aH, const bf16* aL,
                                           const bf16* bH, const bf16* bL,
                                           int ksteps, FragC (&acc)[2][2],
                                           int row0, int col0)
{
    for (int ks = 0; ks < ksteps; ++ks) {
        FragA faH[2], faL[2];
        FragB fbH[2], fbL[2];
#pragma unroll
        for (int i = 0; i < 2; ++i) {
            wmma::load_matrix_sync(faH[i], aH + (row0 + 16 * i) * PA + ks * 16, PA);
            wmma::load_matrix_sync(faL[i], aL + (row0 + 16 * i) * PA + ks * 16, PA);
        }
#pragma unroll
        for (int j = 0; j < 2; ++j) {
            wmma::load_matrix_sync(fbH[j], bH + (ks * 16) * PW + col0 + 16 * j, PW);
            wmma::load_matrix_sync(fbL[j], bL + (ks * 16) * PW + col0 + 16 * j, PW);
        }
#pragma unroll
        for (int i = 0; i < 2; ++i)
#pragma unroll
            for (int j = 0; j < 2; ++j) {
                wmma::mma_sync(acc[i][j], faH[i], fbH[j], acc[i][j]);
                wmma::mma_sync(acc[i][j], faH[i], fbL[j], acc[i][j]);
                wmma::mma_sync(acc[i][j], faL[i], fbH[j], acc[i][j]);
            }
    }
}

__global__ __launch_bounds__(NT, 1)
void biflow_wmma(const float* __restrict__ x,
                 const float* __restrict__ ctx,
                 const float* __restrict__ te,
                 const float* __restrict__ b1,
                 const float* __restrict__ b2,
                 const float* __restrict__ b3,
                 const float* __restrict__ bs,
                 const float* __restrict__ bt,
                 const int*   __restrict__ perm,
                 const int*   __restrict__ idx_a,
                 const int*   __restrict__ idx_b,
                 float* __restrict__ out)
{
    extern __shared__ char smem[];
    bf16*  actH = (bf16*)(smem + SM_ACT);
    bf16*  actL = actH + ALO;
    bf16*  wb   = (bf16*)(smem + SM_WB);
    float* cbuf = (float*)(smem + SM_WB);
    float* zt   = (float*)(smem + SM_ZT);
    float* ldet = (float*)(smem + SM_LDET);
    int* sa_s = (int*)(smem + SM_IDX);
    int* sb_s = sa_s + NL * ADIMV;
    int* da_s = sb_s + NL * ADIMV;
    int* db_s = da_s + NL * ADIMV;

    const int tid  = threadIdx.x;
    const int row0b = blockIdx.x * TB;

    // ---- init ----
    for (int idx = tid; idx < TB * DIMV; idx += NT) {
        int r = idx / DIMV, c = idx % DIMV;
        zt[r * ZP + c] = x[(long long)(row0b + r) * DIMV + c];
    }
    if (tid < TB) ldet[tid] = 0.0f;
    if (tid < NL * ADIMV) {
        int l = tid / ADIMV;
        int ia = idx_a[tid], ib = idx_b[tid];
        da_s[tid] = ia; db_s[tid] = ib;
        sa_s[tid] = perm[l * DIMV + ia];
        sb_s[tid] = perm[l * DIMV + ib];
    }
    __syncthreads();

    const int w = tid >> 5;
    const int wr = w >> 2, wc = w & 3;
    const int row0 = wr * 32, col0 = wc * 32, col0h = wc * 16;

    // epilogue mapping
    const int er = tid >> 2, ec = (tid & 3) * 32;

    const float* ctxb = ctx + (long long)row0b * HHV;
    const float* teb  = te  + (long long)row0b * HHV;

    for (int l = 0; l < NL; ++l) {
        FragC acc[2][2];
#pragma unroll
        for (int i = 0; i < 2; ++i)
#pragma unroll
            for (int j = 0; j < 2; ++j) wmma::fill_fragment(acc[i][j], 0.0f);

        // ---- chunk 1: z_a (K=32) ----
        for (int i = tid; i < 128 * 32; i += NT) {
            int r = i >> 5, k = i & 31;
            float v = (k < ADIMV) ? zt[r * ZP + sa_s[l * ADIMV + k]] : 0.0f;
            split_store(actH + r * PA + k, actL + r * PA + k, v);
        }
        cpimg((char*)wb, g_Wza + (size_t)l * E_ZA, E_ZA * 2, tid);
        __syncthreads();
        gemm_chunk(actH, actL, wb, wb + 32 * PA, 2, acc, row0, col0);
        __syncthreads();

        // ---- chunk 2: ctx (K=128) ----
        for (int i = tid; i < 128 * 64; i += NT) {
            int r = i >> 6, c = (i & 63) * 2;
            float2 v = *(const float2*)&ctxb[r * HHV + c];
            split_store(actH + r * PA + c,     actL + r * PA + c,     v.x);
            split_store(actH + r * PA + c + 1, actL + r * PA + c + 1, v.y);
        }
        cpimg((char*)wb, g_Wc + (size_t)l * E_C, E_C * 2, tid);
        __syncthreads();
        gemm_chunk(actH, actL, wb, wb + 128 * PW, 8, acc, row0, col0);
        __syncthreads();

        // ---- chunk 3: te (K=128) ----
        for (int i = tid; i < 128 * 64; i += NT) {
            int r = i >> 6, c = (i & 63) * 2;
            float2 v = *(const float2*)&teb[r * HHV + c];
            split_store(actH + r * PA + c,     actL + r * PA + c,     v.x);
            split_store(actH + r * PA + c + 1, actL + r * PA + c + 1, v.y);
        }
        cpimg((char*)wb, g_Wt_ + (size_t)l * E_C, E_C * 2, tid);
        __syncthreads();
        gemm_chunk(actH, actL, wb, wb + 128 * PW, 8, acc, row0, col0);
        __syncthreads();

        // ---- epilogue GEMM1 -> h1 in actA (in place) ----
#pragma unroll
        for (int i = 0; i < 2; ++i)
#pragma unroll
            for (int j = 0; j < 2; ++j)
                wmma::store_matrix_sync(cbuf + (row0 + 16 * i) * PC + col0 + 16 * j,
                                        acc[i][j], PC, wmma::mem_row_major);
        __syncthreads();
        {
            const float* bias = b1 + l * HHV;
            for (int jp = 0; jp < 16; ++jp) {
                int c = ec + 2 * jp;
                float v0 = silu_f(cbuf[er * PC + c]     + bias[c]);
                float v1 = silu_f(cbuf[er * PC + c + 1] + bias[c + 1]);
                split_store(actH + er * PA + c,     actL + er * PA + c,     v0);
                split_store(actH + er * PA + c + 1, actL + er * PA + c + 1, v1);
            }
        }
        __syncthreads();

        // ---- GEMM2 / GEMM3 ----
        for (int g = 0; g < 2; ++g) {
#pragma unroll
            for (int i = 0; i < 2; ++i)
#pragma unroll
                for (int j = 0; j < 2; ++j) wmma::fill_fragment(acc[i][j], 0.0f);
            const bf16* wsrc = (g == 0) ? g_W2 : g_W3;
            cpimg((char*)wb, wsrc + (size_t)l * E_C, E_C * 2, tid);
            __syncthreads();
            gemm_chunk(actH, actL, wb, wb + 128 * PW, 8, acc, row0, col0);
            __syncthreads();
#pragma unroll
            for (int i = 0; i < 2; ++i)
#pragma unroll
                for (int j = 0; j < 2; ++j)
                    wmma::store_matrix_sync(cbuf + (row0 + 16 * i) * PC + col0 + 16 * j,
                                            acc[i][j], PC, wmma::mem_row_major);
            __syncthreads();
            const float* bias = (g == 0) ? (b2 + l * HHV) : (b3 + l * HHV);
            for (int jp = 0; jp < 16; ++jp) {
                int c = ec + 2 * jp;
                float v0 = silu_f(cbuf[er * PC + c]     + bias[c]);
                float v1 = silu_f(cbuf[er * PC + c + 1] + bias[c + 1]);
                split_store(actH + er * PA + c,     actL + er * PA + c,     v0);
                split_store(actH + er * PA + c + 1, actL + er * PA + c + 1, v1);
            }
            __syncthreads();
        }

        // ---- heads: C[128x64] = h3 @ [Ws|Wt|0] ----
        {
            FragC acc2[2];
            wmma::fill_fragment(acc2[0], 0.0f);
            wmma::fill_fragment(acc2[1], 0.0f);
            cpimg((char*)wb, g_Whd + (size_t)l * E_HD, E_HD * 2, tid);
            __syncthreads();
            const bf16* bH = wb;
            const bf16* bL = wb + 128 * PH;
            for (int ks = 0; ks < 8; ++ks) {
                FragA faH[2], faL[2];
                FragB fbH, fbL;
#pragma unroll
                for (int i = 0; i < 2; ++i) {
                    wmma::load_matrix_sync(faH[i], actH + (row0 + 16 * i) * PA + ks * 16, PA);
                    wmma::load_matrix_sync(faL[i], actL + (row0 + 16 * i) * PA + ks * 16, PA);
                }
                wmma::load_matrix_sync(fbH, bH + (ks * 16) * PH + col0h, PH);
                wmma::load_matrix_sync(fbL, bL + (ks * 16) * PH + col0h, PH);
#pragma unroll
                for (int i = 0; i < 2; ++i) {
                    wmma::mma_sync(acc2[i], faH[i], fbH, acc2[i]);
                    wmma::mma_sync(acc2[i], faH[i], fbL, acc2[i]);
                    wmma::mma_sync(acc2[i], faL[i], fbH, acc2[i]);
                }
            }
            __syncthreads();
#pragma unroll
            for (int i = 0; i < 2; ++i)
                wmma::store_matrix_sync(cbuf + (row0 + 16 * i) * PCH + col0h,
                                        acc2[i], PCH, wmma::mem_row_major);
            __syncthreads();
        }

        // ---- coupling: 128 threads, each owns one row ----
        if (tid < 128) {
            float sv[ADIMV], tv[ADIMV];
#pragma unroll
            for (int j = 0; j < ADIMV; ++j) {
                float s = cbuf[tid * PCH + j] + bs[l * ADIMV + j];
                sv[j] = fminf(fmaxf(s, -CLIPV), CLIPV);
                tv[j] = cbuf[tid * PCH + ADIMV + j] + bt[l * ADIMV + j];
            }
            float zan[ADIMV], ybn[ADIMV], lsum = 0.0f;
#pragma unroll
            for (int j = 0; j < ADIMV; ++j) {
                float zb = zt[tid * ZP + sb_s[l * ADIMV + j]];
                ybn[j] = fmaf(zb, __expf(sv[j]), tv[j]);
                zan[j] = zt[tid * ZP + sa_s[l * ADIMV + j]];
                lsum += sv[j];
            }
#pragma unroll
            for (int j = 0; j < ADIMV; ++j) {
                zt[tid * ZP + da_s[l * ADIMV + j]] = zan[j];
                zt[tid * ZP + db_s[l * ADIMV + j]] = ybn[j];
            }
            ldet[tid] += lsum;
        }
        __syncthreads();
    }

    // ---- output: z (B x 40) then logdet (B) ----
    for (int idx = tid; idx < TB * DIMV; idx += NT) {
        int r = idx / DIMV, c = idx % DIMV;
        out[(long long)(row0b + r) * DIMV + c] = zt[r * ZP + c];
    }
    if (tid < TB)
        out[(long long)BATCH * DIMV + row0b + tid] = ldet[tid];
}

extern "C" void kernel_launch(void* const* d_in, const int* in_sizes, int n_in,
                              void* d_out, int out_size) {
    const float* x    = (const float*)d_in[0];
    const float* ctx  = (const float*)d_in[1];
    const float* te   = (const float*)d_in[2];
    const float* W1   = (const float*)d_in[3];
    const float* b1   = (const float*)d_in[4];
    const float* W2   = (const float*)d_in[5];
    const float* b2   = (const float*)d_in[6];
    const float* W3   = (const float*)d_in[7];
    const float* b3   = (const float*)d_in[8];
    const float* Ws   = (const float*)d_in[9];
    const float* bs   = (const float*)d_in[10];
    const float* Wt   = (const float*)d_in[11];
    const float* bt   = (const float*)d_in[12];
    const int*   perm = (const int*)d_in[13];
    const int*   ia   = (const int*)d_in[14];
    const int*   ib   = (const int*)d_in[15];
    float* out = (float*)d_out;

    prep_weights<<<512, 256>>>(W1, W2, W3, Ws, Wt);

    cudaFuncSetAttribute(biflow_wmma,
                         cudaFuncAttributeMaxDynamicSharedMemorySize, SMEM_TOTAL);

    biflow_wmma<<<BATCH / TB, NT, SMEM_TOTAL>>>(
        x, ctx, te, b1, b2, b3, bs, bt, perm, ia, ib, out);
}

// round 12
// speedup vs baseline: 1.9361x; 1.3558x over previous
#include <cuda_runtime.h>
#include <cuda_bf16.h>
#include <mma.h>
#include <cstdint>

using namespace nvcuda;

// Problem constants
#define NL    6
#define DIMV  40
#define ADIMV 20
#define HHV   128
#define DINV  276
#define BATCH 131072
#define CLIPV 2.0f

#define TB 128
#define NT 512
#define ZP 44

// pitches
#define PA 136      // activation tile pitch (bf16 elems)
#define PW 136      // weight tile pitch (bf16 elems)
#define PC 132      // C staging pitch (f32 elems)
#define PCH 68      // heads C staging pitch (f32)
#define PH 72       // heads weight pitch (bf16)

#define ALO (128*PA)        // act lo-tile element offset

// per-layer weight image element counts (hi tile + lo tile)
#define E_ZA  (2*32*PA)     // 8704
#define E_C   (2*128*PW)    // 34816
#define E_HD  (2*128*PH)    // 18432

// SMEM byte offsets (flow kernel)
#define SM_ACT  0
#define SM_WB   (2*128*PA*2)                 // 69632
#define SM_ZT   (SM_WB + 2*128*PW*2)         // 139264
#define SM_LDET (SM_ZT + TB*ZP*4)            // 161792
#define SM_IDX  (SM_LDET + TB*4)             // 162304
#define SMEM_TOTAL (SM_IDX + 4*NL*ADIMV*4)   // 164224

// precompute kernel smem: act + wbuf only
#define SMEM_PRE (SM_WB + E_C*2)             // 139264

typedef __nv_bfloat16 bf16;

// pre-split, pre-laid-out weight images (hi tile then lo tile, exact SMEM image)
__device__ __align__(16) bf16 g_Wza[NL * E_ZA];
__device__ __align__(16) bf16 g_Wc [NL * E_C];
__device__ __align__(16) bf16 g_Wt_[NL * E_C];
__device__ __align__(16) bf16 g_W2 [NL * E_C];
__device__ __align__(16) bf16 g_W3 [NL * E_C];
__device__ __align__(16) bf16 g_Whd[NL * E_HD];

// hoisted ctx/te contribution to GEMM1: U[l][row][n], f32
__device__ float g_U[(size_t)NL * BATCH * HHV];

__device__ __forceinline__ void split_store(bf16* hi_p, bf16* lo_p, float v) {
    bf16 h = __float2bfloat16(v);
    bf16 lo = __float2bfloat16(v - __bfloat162float(h));
    *hi_p = h; *lo_p = lo;
}

__global__ void prep_weights(const float* __restrict__ W1,
                             const float* __restrict__ W2,
                             const float* __restrict__ W3,
                             const float* __restrict__ Ws,
                             const float* __restrict__ Wt)
{
    int stride = gridDim.x * blockDim.x;
    int tid0 = blockIdx.x * blockDim.x + threadIdx.x;

    // za: K=32 (rows 20..31 zero), N cols 0..135 (>=128 zero)
    for (int t = tid0; t < NL * 32 * PA; t += stride) {
        int c = t % PA, k = (t / PA) % 32, l = t / (PA * 32);
        float v = (k < ADIMV && c < HHV) ? W1[((long long)l * DINV + k) * HHV + c] : 0.0f;
        bf16* base = g_Wza + (size_t)l * E_ZA;
        split_store(base + k * PA + c, base + 32 * PA + k * PA + c, v);
    }
    // ctx / te / W2 / W3: K=128
    for (int t = tid0; t < NL * 128 * PW; t += stride) {
        int c = t % PW, k = (t / PW) % 128, l = t / (PW * 128);
        float vc = 0.f, vt = 0.f, v2 = 0.f, v3 = 0.f;
        if (c < HHV) {
            vc = W1[((long long)l * DINV + ADIMV + k) * HHV + c];
            vt = W1[((long long)l * DINV + ADIMV + HHV + k) * HHV + c];
            v2 = W2[((long long)l * HHV + k) * HHV + c];
            v3 = W3[((long long)l * HHV + k) * HHV + c];
        }
        size_t o = (size_t)l * E_C + (size_t)k * PW + c;
        size_t olo = o + (size_t)128 * PW;
        split_store(g_Wc + o,  g_Wc + olo,  vc);
        split_store(g_Wt_ + o, g_Wt_ + olo, vt);
        split_store(g_W2 + o,  g_W2 + olo,  v2);
        split_store(g_W3 + o,  g_W3 + olo,  v3);
    }
    // heads: K=128, N=64 packed [Ws(20)|Wt(20)|zeros]
    for (int t = tid0; t < NL * 128 * PH; t += stride) {
        int c = t % PH, k = (t / PH) % 128, l = t / (PH * 128);
        float v = 0.0f;
        if (c < ADIMV)           v = Ws[((long long)l * HHV + k) * ADIMV + c];
        else if (c < 2 * ADIMV)  v = Wt[((long long)l * HHV + k) * ADIMV + (c - ADIMV)];
        bf16* base = g_Whd + (size_t)l * E_HD;
        split_store(base + k * PH + c, base + 128 * PH + k * PH + c, v);
    }
}

__device__ __forceinline__ float silu_f(float v) { return v / (1.0f + __expf(-v)); }

__device__ __forceinline__ void cpimg(char* dst, const bf16* src, int bytes, int tid) {
    float4* d = (float4*)dst;
    const float4* s = (const float4*)src;
    int n = bytes >> 4;
    for (int i = tid; i < n; i += NT) d[i] = s[i];
}

typedef wmma::fragment<wmma::matrix_a, 16, 16, 16, bf16, wmma::row_major> FragA;
typedef wmma::fragment<wmma::matrix_b, 16, 16, 16, bf16, wmma::row_major> FragB;
typedef wmma::fragment<wmma::accumulator, 16, 16, 16, float> FragC;

// 3-term split MMA over one staged K-chunk. acc[2][2] covers 32x32.
__device__ __forceinline__ void gemm_chunk(const bf16* aH, const bf16* aL,
                                           const bf16* bH, const bf16* bL,
                                           int ksteps, FragC (&acc)[2][2],
                                           int row0, int col0)
{
    for (int ks = 0; ks < ksteps; ++ks) {
        FragA faH[2], faL[2];
        FragB fbH[2], fbL[2];
#pragma unroll
        for (int i = 0; i < 2; ++i) {
            wmma::load_matrix_sync(faH[i], aH + (row0 + 16 * i) * PA + ks * 16, PA);
            wmma::load_matrix_sync(faL[i], aL + (row0 + 16 * i) * PA + ks * 16, PA);
        }
#pragma unroll
        for (int j = 0; j < 2; ++j) {
            wmma::load_matrix_sync(fbH[j], bH + (ks * 16) * PW + col0 + 16 * j, PW);
            wmma::load_matrix_sync(fbL[j], bL + (ks * 16) * PW + col0 + 16 * j, PW);
        }
#pragma unroll
        for (int i = 0; i < 2; ++i)
#pragma unroll
            for (int j = 0; j < 2; ++j) {
                wmma::mma_sync(acc[i][j], faH[i], fbH[j], acc[i][j]);
                wmma::mma_sync(acc[i][j], faH[i], fbL[j], acc[i][j]);
                wmma::mma_sync(acc[i][j], faL[i], fbH[j], acc[i][j]);
            }
    }
}

// ================= precompute: U[l] = ctx @ W1c[l] + te @ W1t[l] =================
__global__ __launch_bounds__(NT, 1)
void pre_ctxte(const float* __restrict__ ctx, const float* __restrict__ te)
{
    extern __shared__ char smem[];
    bf16* actH = (bf16*)(smem + SM_ACT);
    bf16* actL = actH + ALO;
    bf16* wb   = (bf16*)(smem + SM_WB);

    const int tid = threadIdx.x;
    const int l = blockIdx.y;
    const long long row0b = (long long)blockIdx.x * TB;

    const int w = tid >> 5;
    const int wr = w >> 2, wc = w & 3;
    const int row0 = wr * 32, col0 = wc * 32;

    FragC acc[2][2];
#pragma unroll
    for (int i = 0; i < 2; ++i)
#pragma unroll
        for (int j = 0; j < 2; ++j) wmma::fill_fragment(acc[i][j], 0.0f);

    for (int g = 0; g < 2; ++g) {
        const float* src = (g == 0) ? (ctx + row0b * HHV) : (te + row0b * HHV);
        for (int i = tid; i < 128 * 64; i += NT) {
            int r = i >> 6, c = (i & 63) * 2;
            float2 v = *(const float2*)&src[r * HHV + c];
            split_store(actH + r * PA + c,     actL + r * PA + c,     v.x);
            split_store(actH + r * PA + c + 1, actL + r * PA + c + 1, v.y);
        }
        const bf16* wsrc = (g == 0) ? g_Wc : g_Wt_;
        cpimg((char*)wb, wsrc + (size_t)l * E_C, E_C * 2, tid);
        __syncthreads();
        gemm_chunk(actH, actL, wb, wb + 128 * PW, 8, acc, row0, col0);
        __syncthreads();
    }

    float* Ubase = g_U + ((size_t)l * BATCH + row0b) * HHV;
#pragma unroll
    for (int i = 0; i < 2; ++i)
#pragma unroll
        for (int j = 0; j < 2; ++j)
            wmma::store_matrix_sync(Ubase + (size_t)(row0 + 16 * i) * HHV + col0 + 16 * j,
                                    acc[i][j], HHV, wmma::mem_row_major);
}

// ================= flow kernel =================
__global__ __launch_bounds__(NT, 1)
void biflow_wmma(const float* __restrict__ x,
                 const float* __restrict__ b1,
                 const float* __restrict__ b2,
                 const float* __restrict__ b3,
                 const float* __restrict__ bs,
                 const float* __restrict__ bt,
                 const int*   __restrict__ perm,
                 const int*   __restrict__ idx_a,
                 const int*   __restrict__ idx_b,
                 float* __restrict__ out)
{
    extern __shared__ char smem[];
    bf16*  actH = (bf16*)(smem + SM_ACT);
    bf16*  actL = actH + ALO;
    bf16*  wb   = (bf16*)(smem + SM_WB);
    float* cbuf = (float*)(smem + SM_WB);
    float* zt   = (float*)(smem + SM_ZT);
    float* ldet = (float*)(smem + SM_LDET);
    int* sa_s = (int*)(smem + SM_IDX);
    int* sb_s = sa_s + NL * ADIMV;
    int* da_s = sb_s + NL * ADIMV;
    int* db_s = da_s + NL * ADIMV;

    const int tid  = threadIdx.x;
    const int row0b = blockIdx.x * TB;

    // ---- init ----
    for (int idx = tid; idx < TB * DIMV; idx += NT) {
        int r = idx / DIMV, c = idx % DIMV;
        zt[r * ZP + c] = x[(long long)(row0b + r) * DIMV + c];
    }
    if (tid < TB) ldet[tid] = 0.0f;
    if (tid < NL * ADIMV) {
        int l = tid / ADIMV;
        int ia = idx_a[tid], ib = idx_b[tid];
        da_s[tid] = ia; db_s[tid] = ib;
        sa_s[tid] = perm[l * DIMV + ia];
        sb_s[tid] = perm[l * DIMV + ib];
    }
    __syncthreads();

    const int w = tid >> 5;
    const int wr = w >> 2, wc = w & 3;
    const int row0 = wr * 32, col0 = wc * 32, col0h = wc * 16;

    // epilogue mapping
    const int er = tid >> 2, ec = (tid & 3) * 32;

    for (int l = 0; l < NL; ++l) {
        FragC acc[2][2];

        // ---- GEMM1 = U[l] (preloaded) + z_a @ W1a ----
        {
            const float* Ubase = g_U + ((size_t)l * BATCH + row0b) * HHV;
#pragma unroll
            for (int i = 0; i < 2; ++i)
#pragma unroll
                for (int j = 0; j < 2; ++j)
                    wmma::load_matrix_sync(acc[i][j],
                        Ubase + (size_t)(row0 + 16 * i) * HHV + col0 + 16 * j,
                        HHV, wmma::mem_row_major);
        }
        for (int i = tid; i < 128 * 32; i += NT) {
            int r = i >> 5, k = i & 31;
            float v = (k < ADIMV) ? zt[r * ZP + sa_s[l * ADIMV + k]] : 0.0f;
            split_store(actH + r * PA + k, actL + r * PA + k, v);
        }
        cpimg((char*)wb, g_Wza + (size_t)l * E_ZA, E_ZA * 2, tid);
        __syncthreads();
        gemm_chunk(actH, actL, wb, wb + 32 * PA, 2, acc, row0, col0);
        __syncthreads();

        // ---- epilogue GEMM1 -> h1 in act (via cbuf) ----
#pragma unroll
        for (int i = 0; i < 2; ++i)
#pragma unroll
            for (int j = 0; j < 2; ++j)
                wmma::store_matrix_sync(cbuf + (row0 + 16 * i) * PC + col0 + 16 * j,
                                        acc[i][j], PC, wmma::mem_row_major);
        __syncthreads();
        {
            const float* bias = b1 + l * HHV;
            for (int jp = 0; jp < 16; ++jp) {
                int c = ec + 2 * jp;
                float v0 = silu_f(cbuf[er * PC + c]     + bias[c]);
                float v1 = silu_f(cbuf[er * PC + c + 1] + bias[c + 1]);
                split_store(actH + er * PA + c,     actL + er * PA + c,     v0);
                split_store(actH + er * PA + c + 1, actL + er * PA + c + 1, v1);
            }
        }
        __syncthreads();

        // ---- GEMM2 / GEMM3 ----
        for (int g = 0; g < 2; ++g) {
#pragma unroll
            for (int i = 0; i < 2; ++i)
#pragma unroll
                for (int j = 0; j < 2; ++j) wmma::fill_fragment(acc[i][j], 0.0f);
            const bf16* wsrc = (g == 0) ? g_W2 : g_W3;
            cpimg((char*)wb, wsrc + (size_t)l * E_C, E_C * 2, tid);
            __syncthreads();
            gemm_chunk(actH, actL, wb, wb + 128 * PW, 8, acc, row0, col0);
            __syncthreads();
#pragma unroll
            for (int i = 0; i < 2; ++i)
#pragma unroll
                for (int j = 0; j < 2; ++j)
                    wmma::store_matrix_sync(cbuf + (row0 + 16 * i) * PC + col0 + 16 * j,
                                            acc[i][j], PC, wmma::mem_row_major);
            __syncthreads();
            const float* bias = (g == 0) ? (b2 + l * HHV) : (b3 + l * HHV);
            for (int jp = 0; jp < 16; ++jp) {
                int c = ec + 2 * jp;
                float v0 = silu_f(cbuf[er * PC + c]     + bias[c]);
                float v1 = silu_f(cbuf[er * PC + c + 1] + bias[c + 1]);
                split_store(actH + er * PA + c,     actL + er * PA + c,     v0);
                split_store(actH + er * PA + c + 1, actL + er * PA + c + 1, v1);
            }
            __syncthreads();
        }

        // ---- heads: C[128x64] = h3 @ [Ws|Wt|0] ----
        {
            FragC acc2[2];
            wmma::fill_fragment(acc2[0], 0.0f);
            wmma::fill_fragment(acc2[1], 0.0f);
            cpimg((char*)wb, g_Whd + (size_t)l * E_HD, E_HD * 2, tid);
            __syncthreads();
            const bf16* bH = wb;
            const bf16* bL = wb + 128 * PH;
            for (int ks = 0; ks < 8; ++ks) {
                FragA faH[2], faL[2];
                FragB fbH, fbL;
#pragma unroll
                for (int i = 0; i < 2; ++i) {
                    wmma::load_matrix_sync(faH[i], actH + (row0 + 16 * i) * PA + ks * 16, PA);
                    wmma::load_matrix_sync(faL[i], actL + (row0 + 16 * i) * PA + ks * 16, PA);
                }
                wmma::load_matrix_sync(fbH, bH + (ks * 16) * PH + col0h, PH);
                wmma::load_matrix_sync(fbL, bL + (ks * 16) * PH + col0h, PH);
#pragma unroll
                for (int i = 0; i < 2; ++i) {
                    wmma::mma_sync(acc2[i], faH[i], fbH, acc2[i]);
                    wmma::mma_sync(acc2[i], faH[i], fbL, acc2[i]);
                    wmma::mma_sync(acc2[i], faL[i], fbH, acc2[i]);
                }
            }
            __syncthreads();
#pragma unroll
            for (int i = 0; i < 2; ++i)
                wmma::store_matrix_sync(cbuf + (row0 + 16 * i) * PCH + col0h,
                                        acc2[i], PCH, wmma::mem_row_major);
            __syncthreads();
        }

        // ---- coupling: 128 threads, each owns one row ----
        if (tid < 128) {
            float sv[ADIMV], tv[ADIMV];
#pragma unroll
            for (int j = 0; j < ADIMV; ++j) {
                float s = cbuf[tid * PCH + j] + bs[l * ADIMV + j];
                sv[j] = fminf(fmaxf(s, -CLIPV), CLIPV);
                tv[j] = cbuf[tid * PCH + ADIMV + j] + bt[l * ADIMV + j];
            }
            float zan[ADIMV], ybn[ADIMV], lsum = 0.0f;
#pragma unroll
            for (int j = 0; j < ADIMV; ++j) {
                float zb = zt[tid * ZP + sb_s[l * ADIMV + j]];
                ybn[j] = fmaf(zb, __expf(sv[j]), tv[j]);
                zan[j] = zt[tid * ZP + sa_s[l * ADIMV + j]];
                lsum += sv[j];
            }
#pragma unroll
            for (int j = 0; j < ADIMV; ++j) {
                zt[tid * ZP + da_s[l * ADIMV + j]] = zan[j];
                zt[tid * ZP + db_s[l * ADIMV + j]] = ybn[j];
            }
            ldet[tid] += lsum;
        }
        __syncthreads();
    }

    // ---- output: z (B x 40) then logdet (B) ----
    for (int idx = tid; idx < TB * DIMV; idx += NT) {
        int r = idx / DIMV, c = idx % DIMV;
        out[(long long)(row0b + r) * DIMV + c] = zt[r * ZP + c];
    }
    if (tid < TB)
        out[(long long)BATCH * DIMV + row0b + tid] = ldet[tid];
}

extern "C" void kernel_launch(void* const* d_in, const int* in_sizes, int n_in,
                              void* d_out, int out_size) {
    const float* x    = (const float*)d_in[0];
    const float* ctx  = (const float*)d_in[1];
    const float* te   = (const float*)d_in[2];
    const float* W1   = (const float*)d_in[3];
    const float* b1   = (const float*)d_in[4];
    const float* W2   = (const float*)d_in[5];
    const float* b2   = (const float*)d_in[6];
    const float* W3   = (const float*)d_in[7];
    const float* b3   = (const float*)d_in[8];
    const float* Ws   = (const float*)d_in[9];
    const float* bs   = (const float*)d_in[10];
    const float* Wt   = (const float*)d_in[11];
    const float* bt   = (const float*)d_in[12];
    const int*   perm = (const int*)d_in[13];
    const int*   ia   = (const int*)d_in[14];
    const int*   ib   = (const int*)d_in[15];
    float* out = (float*)d_out;

    prep_weights<<<512, 256>>>(W1, W2, W3, Ws, Wt);

    cudaFuncSetAttribute(pre_ctxte,
                         cudaFuncAttributeMaxDynamicSharedMemorySize, SMEM_PRE);
    dim3 pre_grid(BATCH / TB, NL);
    pre_ctxte<<<pre_grid, NT, SMEM_PRE>>>(ctx, te);

    cudaFuncSetAttribute(biflow_wmma,
                         cudaFuncAttributeMaxDynamicSharedMemorySize, SMEM_TOTAL);
    biflow_wmma<<<BATCH / TB, NT, SMEM_TOTAL>>>(
        x, b1, b2, b3, bs, bt, perm, ia, ib, out);
}

// round 13
// speedup vs baseline: 2.1586x; 1.1149x over previous
#include <cuda_runtime.h>
#include <cuda_bf16.h>
#include <cuda_pipeline.h>
#include <mma.h>
#include <cstdint>

using namespace nvcuda;

// Problem constants
#define NL    6
#define DIMV  40
#define ADIMV 20
#define HHV   128
#define DINV  276
#define BATCH 131072
#define CLIPV 2.0f

#define TB 128
#define NT 512
#define ZP 44

// pitches
#define PA 136      // activation tile pitch (bf16 elems)
#define PW 136      // weight tile pitch (bf16 elems)
#define PC 132      // C staging pitch (f32 elems)
#define PCH 68      // heads C staging pitch (f32)
#define PH 72       // heads weight pitch (bf16)

#define ALO (128*PA)        // act lo-tile element offset

// weight image element counts per layer
#define E_ZA  (2*32*PA)     // 8704   (hi32|lo32)
#define E_C   (2*128*PW)    // 34816  (2 chunks of [hi64|lo64])
#define E_HD  (2*128*PH)    // 18432  (2 chunks of [hi64|lo64])

// chunk sizes
#define CHW_ELEM (128*PW)   // elems per MLP chunk (hi64+lo64)
#define CHH_ELEM (128*PH)   // elems per heads chunk
#define CB_MLP (CHW_ELEM*2) // bytes 34816
#define CB_ZA  (E_ZA*2)     // bytes 17408
#define CB_HD  (CHH_ELEM*2) // bytes 18432

#define WBUF_B 34816        // one weight buffer (bytes)

// ---- flow kernel SMEM layout (bytes) ----
#define SM_ACT  0
#define SM_WB   (2*128*PA*2)                  // 69632
#define SM_CB   (SM_WB + 2*WBUF_B)            // 139264
#define SM_ZT   (SM_CB + 128*PC*4)            // 206848
#define SM_LDET (SM_ZT + TB*ZP*4)             // 229376
#define SM_IDX  (SM_LDET + TB*4)              // 229888
#define SMEM_TOTAL (SM_IDX + 4*NL*ADIMV*4)    // 231808

// ---- pre kernel SMEM layout ----
#define PSM_CTX 0
#define PSM_TE  (2*128*PA*2)                  // 69632
#define PSM_WB  (2*2*128*PA*2)                // 139264
#define SMEM_PRE (PSM_WB + 2*WBUF_B)          // 208896

typedef __nv_bfloat16 bf16;

// weight images (exact SMEM chunk images)
__device__ __align__(16) bf16 g_Wza[NL * E_ZA];
__device__ __align__(16) bf16 g_Wc [NL * E_C];
__device__ __align__(16) bf16 g_Wt_[NL * E_C];
__device__ __align__(16) bf16 g_W2 [NL * E_C];
__device__ __align__(16) bf16 g_W3 [NL * E_C];
__device__ __align__(16) bf16 g_Whd[NL * E_HD];

// hoisted ctx/te contribution to GEMM1: U[l][row][n], f32
__device__ float g_U[(size_t)NL * BATCH * HHV];

__device__ __forceinline__ void split_store(bf16* hi_p, bf16* lo_p, float v) {
    bf16 h = __float2bfloat16(v);
    bf16 lo = __float2bfloat16(v - __bfloat162float(h));
    *hi_p = h; *lo_p = lo;
}

__global__ void prep_weights(const float* __restrict__ W1,
                             const float* __restrict__ W2,
                             const float* __restrict__ W3,
                             const float* __restrict__ Ws,
                             const float* __restrict__ Wt)
{
    int stride = gridDim.x * blockDim.x;
    int tid0 = blockIdx.x * blockDim.x + threadIdx.x;

    // za: single chunk [hi 32 x PA | lo 32 x PA]
    for (int t = tid0; t < NL * 32 * PA; t += stride) {
        int c = t % PA, k = (t / PA) % 32, l = t / (PA * 32);
        float v = (k < ADIMV && c < HHV) ? W1[((long long)l * DINV + k) * HHV + c] : 0.0f;
        bf16* base = g_Wza + (size_t)l * E_ZA;
        split_store(base + k * PA + c, base + 32 * PA + k * PA + c, v);
    }
    // K=128 kinds: chunked [hi64|lo64][hi64|lo64]
    for (int t = tid0; t < NL * 128 * PW; t += stride) {
        int c = t % PW, k = (t / PW) % 128, l = t / (PW * 128);
        float vc = 0.f, vt = 0.f, v2 = 0.f, v3 = 0.f;
        if (c < HHV) {
            vc = W1[((long long)l * DINV + ADIMV + k) * HHV + c];
            vt = W1[((long long)l * DINV + ADIMV + HHV + k) * HHV + c];
            v2 = W2[((long long)l * HHV + k) * HHV + c];
            v3 = W3[((long long)l * HHV + k) * HHV + c];
        }
        int chunk = k >> 6, kr = k & 63;
        size_t o_hi = (size_t)l * E_C + (size_t)chunk * CHW_ELEM + (size_t)kr * PW + c;
        size_t o_lo = o_hi + (size_t)64 * PW;
        split_store(g_Wc + o_hi,  g_Wc + o_lo,  vc);
        split_store(g_Wt_ + o_hi, g_Wt_ + o_lo, vt);
        split_store(g_W2 + o_hi,  g_W2 + o_lo,  v2);
        split_store(g_W3 + o_hi,  g_W3 + o_lo,  v3);
    }
    // heads: chunked, N=64 packed [Ws(20)|Wt(20)|zeros]
    for (int t = tid0; t < NL * 128 * PH; t += stride) {
        int c = t % PH, k = (t / PH) % 128, l = t / (PH * 128);
        float v = 0.0f;
        if (c < ADIMV)           v = Ws[((long long)l * HHV + k) * ADIMV + c];
        else if (c < 2 * ADIMV)  v = Wt[((long long)l * HHV + k) * ADIMV + (c - ADIMV)];
        int chunk = k >> 6, kr = k & 63;
        size_t o_hi = (size_t)l * E_HD + (size_t)chunk * CHH_ELEM + (size_t)kr * PH + c;
        split_store(g_Whd + o_hi, g_Whd + o_hi + 64 * PH, v);
    }
}

__device__ __forceinline__ float silu_f(float v) { return v / (1.0f + __expf(-v)); }

// async chunk copy: every thread issues its slice, then commits one group
__device__ __forceinline__ void cpa(void* dst, const void* src, int bytes, int tid) {
    char* d = (char*)dst;
    const char* s = (const char*)src;
    for (int i = tid * 16; i < bytes; i += NT * 16)
        __pipeline_memcpy_async(d + i, s + i, 16);
    __pipeline_commit();
}

typedef wmma::fragment<wmma::matrix_a, 16, 16, 16, bf16, wmma::row_major> FragA;
typedef wmma::fragment<wmma::matrix_b, 16, 16, 16, bf16, wmma::row_major> FragB;
typedef wmma::fragment<wmma::accumulator, 16, 16, 16, float> FragC;

// 3-term split MMA: acc[2][2] covers rows row0..row0+31, cols col0..col0+31.
// aH/aL: act base (already offset to this K-chunk's first column).
// bH/bL: staged weight chunk (kr rows x PW).
__device__ __forceinline__ void gemm_chunk(const bf16* aH, const bf16* aL,
                                           const bf16* bH, const bf16* bL,
                                           int ksteps, FragC (&acc)[2][2],
                                           int row0, int col0)
{
    for (int ks = 0; ks < ksteps; ++ks) {
        FragA faH[2], faL[2];
        FragB fbH[2], fbL[2];
#pragma unroll
        for (int i = 0; i < 2; ++i) {
            wmma::load_matrix_sync(faH[i], aH + (row0 + 16 * i) * PA + ks * 16, PA);
            wmma::load_matrix_sync(faL[i], aL + (row0 + 16 * i) * PA + ks * 16, PA);
        }
#pragma unroll
        for (int j = 0; j < 2; ++j) {
            wmma::load_matrix_sync(fbH[j], bH + (ks * 16) * PW + col0 + 16 * j, PW);
            wmma::load_matrix_sync(fbL[j], bL + (ks * 16) * PW + col0 + 16 * j, PW);
        }
#pragma unroll
        for (int i = 0; i < 2; ++i)
#pragma unroll
            for (int j = 0; j < 2; ++j) {
                wmma::mma_sync(acc[i][j], faH[i], fbH[j], acc[i][j]);
                wmma::mma_sync(acc[i][j], faH[i], fbL[j], acc[i][j]);
                wmma::mma_sync(acc[i][j], faL[i], fbH[j], acc[i][j]);
            }
    }
}

// ================= precompute: U[l] = ctx @ W1c[l] + te @ W1t[l] =================
__global__ __launch_bounds__(NT, 1)
void pre_ctxte(const float* __restrict__ ctx, const float* __restrict__ te)
{
    extern __shared__ char smem[];
    bf16* cH = (bf16*)(smem + PSM_CTX);
    bf16* cL = cH + ALO;
    bf16* tH = (bf16*)(smem + PSM_TE);
    bf16* tL = tH + ALO;
    bf16* wbA = (bf16*)(smem + PSM_WB);
    bf16* wbB = (bf16*)(smem + PSM_WB + WBUF_B);

    const int tid = threadIdx.x;
    const long long row0b = (long long)blockIdx.x * TB;

    const int w = tid >> 5;
    const int wr = w >> 2, wc = w & 3;
    const int row0 = wr * 32, col0 = wc * 32;

    // build both act tiles once
    {
        const float* sc = ctx + row0b * HHV;
        const float* st = te + row0b * HHV;
        for (int i = tid; i < 128 * 64; i += NT) {
            int r = i >> 6, c = (i & 63) * 2;
            float2 v = *(const float2*)&sc[r * HHV + c];
            split_store(cH + r * PA + c,     cL + r * PA + c,     v.x);
            split_store(cH + r * PA + c + 1, cL + r * PA + c + 1, v.y);
            float2 u = *(const float2*)&st[r * HHV + c];
            split_store(tH + r * PA + c,     tL + r * PA + c,     u.x);
            split_store(tH + r * PA + c + 1, tL + r * PA + c + 1, u.y);
        }
    }

    for (int l = 0; l < NL; ++l) {
        const bf16* wc_ = g_Wc + (size_t)l * E_C;
        const bf16* wt_ = g_Wt_ + (size_t)l * E_C;

        FragC acc[2][2];
#pragma unroll
        for (int i = 0; i < 2; ++i)
#pragma unroll
            for (int j = 0; j < 2; ++j) wmma::fill_fragment(acc[i][j], 0.0f);

        cpa(wbA, wc_, CB_MLP, tid);              // g0: Wc chunk0
        cpa(wbB, wc_ + CHW_ELEM, CB_MLP, tid);   // g1: Wc chunk1
        __pipeline_wait_prior(1); __syncthreads();
        gemm_chunk(cH, cL, wbA, wbA + 64 * PW, 4, acc, row0, col0);
        __syncthreads();
        cpa(wbA, wt_, CB_MLP, tid);              // g2: Wt chunk0
        __pipeline_wait_prior(1); __syncthreads();
        gemm_chunk(cH + 64, cL + 64, wbB, wbB + 64 * PW, 4, acc, row0, col0);
        __syncthreads();
        cpa(wbB, wt_ + CHW_ELEM, CB_MLP, tid);   // g3: Wt chunk1
        __pipeline_wait_prior(1); __syncthreads();
        gemm_chunk(tH, tL, wbA, wbA + 64 * PW, 4, acc, row0, col0);
        __pipeline_wait_prior(0); __syncthreads();
        gemm_chunk(tH + 64, tL + 64, wbB, wbB + 64 * PW, 4, acc, row0, col0);
        __syncthreads();

        float* Ubase = g_U + ((size_t)l * BATCH + row0b) * HHV;
#pragma unroll
        for (int i = 0; i < 2; ++i)
#pragma unroll
            for (int j = 0; j < 2; ++j)
                wmma::store_matrix_sync(Ubase + (size_t)(row0 + 16 * i) * HHV + col0 + 16 * j,
                                        acc[i][j], HHV, wmma::mem_row_major);
    }
}

// ================= flow kernel =================
__global__ __launch_bounds__(NT, 1)
void biflow_wmma(const float* __restrict__ x,
                 const float* __restrict__ b1,
                 const float* __restrict__ b2,
                 const float* __restrict__ b3,
                 const float* __restrict__ bs,
                 const float* __restrict__ bt,
                 const int*   __restrict__ perm,
                 const int*   __restrict__ idx_a,
                 const int*   __restrict__ idx_b,
                 float* __restrict__ out)
{
    extern __shared__ char smem[];
    bf16*  actH = (bf16*)(smem + SM_ACT);
    bf16*  actL = actH + ALO;
    bf16*  wbA  = (bf16*)(smem + SM_WB);
    bf16*  wbB  = (bf16*)(smem + SM_WB + WBUF_B);
    float* cbuf = (float*)(smem + SM_CB);
    float* zt   = (float*)(smem + SM_ZT);
    float* ldet = (float*)(smem + SM_LDET);
    int* sa_s = (int*)(smem + SM_IDX);
    int* sb_s = sa_s + NL * ADIMV;
    int* da_s = sb_s + NL * ADIMV;
    int* db_s = da_s + NL * ADIMV;

    const int tid  = threadIdx.x;
    const int row0b = blockIdx.x * TB;

    // ---- init ----
    for (int idx = tid; idx < TB * DIMV; idx += NT) {
        int r = idx / DIMV, c = idx % DIMV;
        zt[r * ZP + c] = x[(long long)(row0b + r) * DIMV + c];
    }
    if (tid < TB) ldet[tid] = 0.0f;
    if (tid < NL * ADIMV) {
        int l = tid / ADIMV;
        int ia = idx_a[tid], ib = idx_b[tid];
        da_s[tid] = ia; db_s[tid] = ib;
        sa_s[tid] = perm[l * DIMV + ia];
        sb_s[tid] = perm[l * DIMV + ib];
    }
    __syncthreads();

    const int w = tid >> 5;
    const int wr = w >> 2, wc = w & 3;
    const int row0 = wr * 32, col0 = wc * 32, col0h = wc * 16;
    const int er = tid >> 2, ec = (tid & 3) * 32;

    for (int l = 0; l < NL; ++l) {
        const bf16* wza = g_Wza + (size_t)l * E_ZA;
        const bf16* w2  = g_W2 + (size_t)l * E_C;
        const bf16* w3  = g_W3 + (size_t)l * E_C;
        const bf16* whd = g_Whd + (size_t)l * E_HD;

        FragC acc[2][2];

        // ---- prefetch za + W2c0; meanwhile build za act and load U ----
        cpa(wbA, wza, CB_ZA, tid);               // g0
        cpa(wbB, w2, CB_MLP, tid);               // g1
        {
            const float* Ubase = g_U + ((size_t)l * BATCH + row0b) * HHV;
#pragma unroll
            for (int i = 0; i < 2; ++i)
#pragma unroll
                for (int j = 0; j < 2; ++j)
                    wmma::load_matrix_sync(acc[i][j],
                        Ubase + (size_t)(row0 + 16 * i) * HHV + col0 + 16 * j,
                        HHV, wmma::mem_row_major);
        }
        for (int i = tid; i < 128 * 32; i += NT) {
            int r = i >> 5, k = i & 31;
            float v = (k < ADIMV) ? zt[r * ZP + sa_s[l * ADIMV + k]] : 0.0f;
            split_store(actH + r * PA + k, actL + r * PA + k, v);
        }
        __pipeline_wait_prior(1); __syncthreads();         // za(A) + act ready
        gemm_chunk(actH, actL, wbA, wbA + 32 * PA, 2, acc, row0, col0);
        __syncthreads();                                   // A free
        cpa(wbA, w2 + CHW_ELEM, CB_MLP, tid);              // g2: W2c1
#pragma unroll
        for (int i = 0; i < 2; ++i)
#pragma unroll
            for (int j = 0; j < 2; ++j)
                wmma::store_matrix_sync(cbuf + (row0 + 16 * i) * PC + col0 + 16 * j,
                                        acc[i][j], PC, wmma::mem_row_major);
        __syncthreads();                                   // cbuf visible
        {
            const float* bias = b1 + l * HHV;
            for (int jp = 0; jp < 16; ++jp) {
                int c = ec + 2 * jp;
                float v0 = silu_f(cbuf[er * PC + c]     + bias[c]);
                float v1 = silu_f(cbuf[er * PC + c + 1] + bias[c + 1]);
                split_store(actH + er * PA + c,     actL + er * PA + c,     v0);
                split_store(actH + er * PA + c + 1, actL + er * PA + c + 1, v1);
            }
        }

        // ---- GEMM2 ----
#pragma unroll
        for (int i = 0; i < 2; ++i)
#pragma unroll
            for (int j = 0; j < 2; ++j) wmma::fill_fragment(acc[i][j], 0.0f);
        __pipeline_wait_prior(1); __syncthreads();         // W2c0(B) + act
        gemm_chunk(actH, actL, wbB, wbB + 64 * PW, 4, acc, row0, col0);
        __syncthreads();                                   // B free
        cpa(wbB, w3, CB_MLP, tid);                         // g3: W3c0
        __pipeline_wait_prior(1); __syncthreads();         // W2c1(A)
        gemm_chunk(actH + 64, actL + 64, wbA, wbA + 64 * PW, 4, acc, row0, col0);
        __syncthreads();                                   // A free
        cpa(wbA, w3 + CHW_ELEM, CB_MLP, tid);              // g4: W3c1
#pragma unroll
        for (int i = 0; i < 2; ++i)
#pragma unroll
            for (int j = 0; j < 2; ++j)
                wmma::store_matrix_sync(cbuf + (row0 + 16 * i) * PC + col0 + 16 * j,
                                        acc[i][j], PC, wmma::mem_row_major);
        __syncthreads();
        {
            const float* bias = b2 + l * HHV;
            for (int jp = 0; jp < 16; ++jp) {
                int c = ec + 2 * jp;
                float v0 = silu_f(cbuf[er * PC + c]     + bias[c]);
                float v1 = silu_f(cbuf[er * PC + c + 1] + bias[c + 1]);
                split_store(actH + er * PA + c,     actL + er * PA + c,     v0);
                split_store(actH + er * PA + c + 1, actL + er * PA + c + 1, v1);
            }
        }

        // ---- GEMM3 ----
#pragma unroll
        for (int i = 0; i < 2; ++i)
#pragma unroll
            for (int j = 0; j < 2; ++j) wmma::fill_fragment(acc[i][j], 0.0f);
        __pipeline_wait_prior(1); __syncthreads();         // W3c0(B) + act
        gemm_chunk(actH, actL, wbB, wbB + 64 * PW, 4, acc, row0, col0);
        __syncthreads();                                   // B free
        cpa(wbB, whd, CB_HD, tid);                         // g5: HDc0
        __pipeline_wait_prior(1); __syncthreads();         // W3c1(A)
        gemm_chunk(actH + 64, actL + 64, wbA, wbA + 64 * PW, 4, acc, row0, col0);
        __syncthreads();                                   // A free
        cpa(wbA, whd + CHH_ELEM, CB_HD, tid);              // g6: HDc1
#pragma unroll
        for (int i = 0; i < 2; ++i)
#pragma unroll
            for (int j = 0; j < 2; ++j)
                wmma::store_matrix_sync(cbuf + (row0 + 16 * i) * PC + col0 + 16 * j,
                                        acc[i][j], PC, wmma::mem_row_major);
        __syncthreads();
        {
            const float* bias = b3 + l * HHV;
            for (int jp = 0; jp < 16; ++jp) {
                int c = ec + 2 * jp;
                float v0 = silu_f(cbuf[er * PC + c]     + bias[c]);
                float v1 = silu_f(cbuf[er * PC + c + 1] + bias[c + 1]);
                split_store(actH + er * PA + c,     actL + er * PA + c,     v0);
                split_store(actH + er * PA + c + 1, actL + er * PA + c + 1, v1);
            }
        }

        // ---- heads ----
        {
            FragC acc2[2];
            wmma::fill_fragment(acc2[0], 0.0f);
            wmma::fill_fragment(acc2[1], 0.0f);
            __pipeline_wait_prior(1); __syncthreads();     // HDc0(B) + act
            for (int q = 0; q < 2; ++q) {
                const bf16* bH = (q == 0) ? wbB : wbA;
                const bf16* bL = bH + 64 * PH;
                const bf16* aHq = actH + q * 64;
                const bf16* aLq = actL + q * 64;
                for (int ks = 0; ks < 4; ++ks) {
                    FragA faH[2], faL[2];
                    FragB fbH, fbL;
#pragma unroll
                    for (int i = 0; i < 2; ++i) {
                        wmma::load_matrix_sync(faH[i], aHq + (row0 + 16 * i) * PA + ks * 16, PA);
                        wmma::load_matrix_sync(faL[i], aLq + (row0 + 16 * i) * PA + ks * 16, PA);
                    }
                    wmma::load_matrix_sync(fbH, bH + (ks * 16) * PH + col0h, PH);
                    wmma::load_matrix_sync(fbL, bL + (ks * 16) * PH + col0h, PH);
#pragma unroll
                    for (int i = 0; i < 2; ++i) {
                        wmma::mma_sync(acc2[i], faH[i], fbH, acc2[i]);
                        wmma::mma_sync(acc2[i], faH[i], fbL, acc2[i]);
                        wmma::mma_sync(acc2[i], faL[i], fbH, acc2[i]);
                    }
                }
                if (q == 0) { __pipeline_wait_prior(0); __syncthreads(); }  // HDc1(A)
            }
            __syncthreads();
#pragma unroll
            for (int i = 0; i < 2; ++i)
                wmma::store_matrix_sync(cbuf + (row0 + 16 * i) * PCH + col0h,
                                        acc2[i], PCH, wmma::mem_row_major);
            __syncthreads();
        }

        // ---- coupling: 128 threads, each owns one row ----
        if (tid < 128) {
            float sv[ADIMV], tv[ADIMV];
#pragma unroll
            for (int j = 0; j < ADIMV; ++j) {
                float s = cbuf[tid * PCH + j] + bs[l * ADIMV + j];
                sv[j] = fminf(fmaxf(s, -CLIPV), CLIPV);
                tv[j] = cbuf[tid * PCH + ADIMV + j] + bt[l * ADIMV + j];
            }
            float zan[ADIMV], ybn[ADIMV], lsum = 0.0f;
#pragma unroll
            for (int j = 0; j < ADIMV; ++j) {
                float zb = zt[tid * ZP + sb_s[l * ADIMV + j]];
                ybn[j] = fmaf(zb, __expf(sv[j]), tv[j]);
                zan[j] = zt[tid * ZP + sa_s[l * ADIMV + j]];
                lsum += sv[j];
            }
#pragma unroll
            for (int j = 0; j < ADIMV; ++j) {
                zt[tid * ZP + da_s[l * ADIMV + j]] = zan[j];
                zt[tid * ZP + db_s[l * ADIMV + j]] = ybn[j];
            }
            ldet[tid] += lsum;
        }
        __syncthreads();
    }

    // ---- output: z (B x 40) then logdet (B) ----
    for (int idx = tid; idx < TB * DIMV; idx += NT) {
        int r = idx / DIMV, c = idx % DIMV;
        out[(long long)(row0b + r) * DIMV + c] = zt[r * ZP + c];
    }
    if (tid < TB)
        out[(long long)BATCH * DIMV + row0b + tid] = ldet[tid];
}

extern "C" void kernel_launch(void* const* d_in, const int* in_sizes, int n_in,
                              void* d_out, int out_size) {
    const float* x    = (const float*)d_in[0];
    const float* ctx  = (const float*)d_in[1];
    const float* te   = (const float*)d_in[2];
    const float* W1   = (const float*)d_in[3];
    const float* b1   = (const float*)d_in[4];
    const float* W2   = (const float*)d_in[5];
    const float* b2   = (const float*)d_in[6];
    const float* W3   = (const float*)d_in[7];
    const float* b3   = (const float*)d_in[8];
    const float* Ws   = (const float*)d_in[9];
    const float* bs   = (const float*)d_in[10];
    const float* Wt   = (const float*)d_in[11];
    const float* bt   = (const float*)d_in[12];
    const int*   perm = (const int*)d_in[13];
    const int*   ia   = (const int*)d_in[14];
    const int*   ib   = (const int*)d_in[15];
    float* out = (float*)d_out;

    prep_weights<<<512, 256>>>(W1, W2, W3, Ws, Wt);

    cudaFuncSetAttribute(pre_ctxte,
                         cudaFuncAttributeMaxDynamicSharedMemorySize, SMEM_PRE);
    pre_ctxte<<<BATCH / TB, NT, SMEM_PRE>>>(ctx, te);

    cudaFuncSetAttribute(biflow_wmma,
                         cudaFuncAttributeMaxDynamicSharedMemorySize, SMEM_TOTAL);
    biflow_wmma<<<BATCH / TB, NT, SMEM_TOTAL>>>(
        x, b1, b2, b3, bs, bt, perm, ia, ib, out);
}